// round 1
// baseline (speedup 1.0000x reference)
#include <cuda_runtime.h>
#include <math.h>

#define BATCH 4
#define NSEQ  1024
#define CDIM  768
#define NHEAD 12
#define HDIM  64
#define DFFN  3072
#define ROWS  (BATCH*NSEQ)   // 4096

// ---------------- scratch (static device globals; no allocation) ----------------
__device__ float g_h   [ROWS*CDIM];          // ln1 out
__device__ float g_qkv [ROWS*3*CDIM];        // qkv
__device__ float g_S   [50331648];           // 4*12*1024*1024 attention scores (reused for P)
__device__ float g_attn[ROWS*CDIM];          // AV out, [B,N,C]
__device__ float g_x2  [ROWS*CDIM];          // after proj + residual
__device__ float g_h2  [ROWS*CDIM];          // ln2 out
__device__ float g_conv[ROWS*CDIM];          // depthwise conv out
__device__ float g_m   [ROWS*CDIM];          // ln_m out
__device__ float g_ff  [ROWS*DFFN];          // fc1 out

// ---------------- generic tiled fp32 GEMM ----------------
// C[M,N] = alpha * A[M,K] * op(B) (+ bias[n]) (+gelu) (+ res[m,n])
// BT=true : B is [N,K] row-major (ldb = row stride)  -> C = A * B^T
// BT=false: B is [K,N] row-major (ldb = row stride)  -> C = A * B
// Batched: blockIdx.z = bi*inner + hi, offsets = bi*s? + hi*s?2
// EPI: 0 = scale only, 1 = +bias, 2 = +bias then exact GELU, 3 = +bias +res
template<int BM, int BN, int BK, int TM, int TN, bool BT, int EPI>
__global__ void __launch_bounds__(256)
gemm_kernel(const float* __restrict__ A, const float* __restrict__ B,
            float* __restrict__ C,
            int M, int N, int K,
            int lda, int ldb, int ldc,
            long long sA, long long sA2,
            long long sB, long long sB2,
            long long sC, long long sC2, int inner,
            const float* __restrict__ bias,
            const float* __restrict__ res, int ldres,
            float alpha)
{
    constexpr int THREADS = (BM/TM)*(BN/TN);
    __shared__ __align__(16) float As[BK][BM+4];
    __shared__ __align__(16) float Bs[BK][BN+4];

    int z  = blockIdx.z;
    int bi = z / inner;
    int hi = z - bi*inner;
    A += bi*sA + hi*sA2;
    B += bi*sB + hi*sB2;
    C += bi*sC + hi*sC2;

    const int m0  = blockIdx.y * BM;
    const int n0  = blockIdx.x * BN;
    const int tid = threadIdx.x;
    const int tx  = tid % (BN/TN);
    const int ty  = tid / (BN/TN);

    float acc[TM][TN];
    #pragma unroll
    for (int i = 0; i < TM; i++)
        #pragma unroll
        for (int j = 0; j < TN; j++) acc[i][j] = 0.f;

    for (int k0 = 0; k0 < K; k0 += BK) {
        // A tile: BM x BK, float4 along k
        #pragma unroll
        for (int idx = tid; idx < BM*BK/4; idx += THREADS) {
            int m  = idx / (BK/4);
            int kk = (idx - m*(BK/4)) * 4;
            float4 v = *(const float4*)(A + (long long)(m0+m)*lda + k0 + kk);
            As[kk+0][m] = v.x; As[kk+1][m] = v.y; As[kk+2][m] = v.z; As[kk+3][m] = v.w;
        }
        if (BT) {
            #pragma unroll
            for (int idx = tid; idx < BN*BK/4; idx += THREADS) {
                int n  = idx / (BK/4);
                int kk = (idx - n*(BK/4)) * 4;
                float4 v = *(const float4*)(B + (long long)(n0+n)*ldb + k0 + kk);
                Bs[kk+0][n] = v.x; Bs[kk+1][n] = v.y; Bs[kk+2][n] = v.z; Bs[kk+3][n] = v.w;
            }
        } else {
            #pragma unroll
            for (int idx = tid; idx < BK*BN/4; idx += THREADS) {
                int k  = idx / (BN/4);
                int nn = (idx - k*(BN/4)) * 4;
                float4 v = *(const float4*)(B + (long long)(k0+k)*ldb + n0 + nn);
                Bs[k][nn+0] = v.x; Bs[k][nn+1] = v.y; Bs[k][nn+2] = v.z; Bs[k][nn+3] = v.w;
            }
        }
        __syncthreads();

        #pragma unroll
        for (int k = 0; k < BK; k++) {
            float ra[TM], rb[TN];
            #pragma unroll
            for (int i = 0; i < TM; i += 4) {
                float4 t = *(const float4*)&As[k][ty*TM + i];
                ra[i] = t.x; ra[i+1] = t.y; ra[i+2] = t.z; ra[i+3] = t.w;
            }
            #pragma unroll
            for (int j = 0; j < TN; j += 4) {
                float4 t = *(const float4*)&Bs[k][tx*TN + j];
                rb[j] = t.x; rb[j+1] = t.y; rb[j+2] = t.z; rb[j+3] = t.w;
            }
            #pragma unroll
            for (int i = 0; i < TM; i++)
                #pragma unroll
                for (int j = 0; j < TN; j++)
                    acc[i][j] += ra[i] * rb[j];
        }
        __syncthreads();
    }

    #pragma unroll
    for (int i = 0; i < TM; i++) {
        int r = m0 + ty*TM + i;
        #pragma unroll
        for (int j = 0; j < TN; j++) {
            int c = n0 + tx*TN + j;
            float v = acc[i][j] * alpha;
            if (EPI >= 1) v += bias[c];
            if (EPI == 2) v = 0.5f * v * (1.0f + erff(v * 0.70710678118654752f));
            if (EPI == 3) v += res[(long long)r*ldres + c];
            C[(long long)r*ldc + c] = v;
        }
    }
}

// ---------------- LayerNorm (one block per row, C=768) ----------------
__global__ void ln_kernel(const float* __restrict__ in, const float* __restrict__ g,
                          const float* __restrict__ b, float* __restrict__ out)
{
    int row = blockIdx.x;
    const float* x = in + (long long)row * CDIM;
    float* o = out + (long long)row * CDIM;
    int tid = threadIdx.x;
    float xv[3];
    float s = 0.f, ss = 0.f;
    #pragma unroll
    for (int i = 0; i < 3; i++) {
        float v = x[tid + i*256];
        xv[i] = v; s += v; ss += v*v;
    }
    __shared__ float red[64];
    #pragma unroll
    for (int off = 16; off > 0; off >>= 1) {
        s  += __shfl_down_sync(0xffffffffu, s,  off);
        ss += __shfl_down_sync(0xffffffffu, ss, off);
    }
    int warp = tid >> 5, lane = tid & 31;
    if (lane == 0) { red[warp] = s; red[32+warp] = ss; }
    __syncthreads();
    if (warp == 0) {
        s  = (lane < 8) ? red[lane]    : 0.f;
        ss = (lane < 8) ? red[32+lane] : 0.f;
        #pragma unroll
        for (int off = 4; off > 0; off >>= 1) {
            s  += __shfl_down_sync(0xffffffffu, s,  off);
            ss += __shfl_down_sync(0xffffffffu, ss, off);
        }
        if (lane == 0) { red[0] = s; red[1] = ss; }
    }
    __syncthreads();
    float mu   = red[0] * (1.f/CDIM);
    float var  = red[1] * (1.f/CDIM) - mu*mu;
    float rstd = rsqrtf(var + 1e-5f);
    #pragma unroll
    for (int i = 0; i < 3; i++) {
        int c = tid + i*256;
        o[c] = (xv[i] - mu) * rstd * g[c] + b[c];
    }
}

// ---------------- head-mix -> softmax -> head-mix (in place on S) ----------------
// one block per (b,n); 12x1024 score slab in dynamic smem, stride 1025 (conflict-free cols)
#define SHP 1025
__global__ void mixsoftmax_kernel(float* __restrict__ S,
                                  const float* __restrict__ tb,
                                  const float* __restrict__ ta)
{
    extern __shared__ float sh[];                 // 12 * SHP floats
    __shared__ float tbs[144], tas[144];
    int bn = blockIdx.x;
    int b = bn >> 10, n = bn & 1023;
    int tid = threadIdx.x;
    if (tid < 144) { tbs[tid] = tb[tid]; tas[tid] = ta[tid]; }
    const long long HS = 1024LL*1024LL;
    long long base = ((long long)b*NHEAD*1024 + n) * 1024;
    #pragma unroll
    for (int h = 0; h < NHEAD; h++)
        for (int m = tid; m < 1024; m += 256)
            sh[h*SHP + m] = S[base + h*HS + m];
    __syncthreads();

    // mix before (column-owned, in place, race-free)
    #pragma unroll
    for (int j = 0; j < 4; j++) {
        int m = tid + j*256;
        float s[NHEAD], a[NHEAD];
        #pragma unroll
        for (int h = 0; h < NHEAD; h++) s[h] = sh[h*SHP + m];
        #pragma unroll
        for (int g = 0; g < NHEAD; g++) {
            float v = 0.f;
            #pragma unroll
            for (int h = 0; h < NHEAD; h++) v += tbs[g*12 + h] * s[h];
            a[g] = v;
        }
        #pragma unroll
        for (int g = 0; g < NHEAD; g++) sh[g*SHP + m] = a[g];
    }
    __syncthreads();

    // softmax per head row (warp per row)
    int warp = tid >> 5, lane = tid & 31;
    for (int h = warp; h < NHEAD; h += 8) {
        float* row = sh + h*SHP;
        float mx = -1e30f;
        for (int m = lane; m < 1024; m += 32) mx = fmaxf(mx, row[m]);
        #pragma unroll
        for (int off = 16; off > 0; off >>= 1) mx = fmaxf(mx, __shfl_xor_sync(0xffffffffu, mx, off));
        float sum = 0.f;
        for (int m = lane; m < 1024; m += 32) {
            float e = __expf(row[m] - mx);
            row[m] = e; sum += e;
        }
        #pragma unroll
        for (int off = 16; off > 0; off >>= 1) sum += __shfl_xor_sync(0xffffffffu, sum, off);
        float inv = 1.f / sum;
        for (int m = lane; m < 1024; m += 32) row[m] *= inv;
    }
    __syncthreads();

    // mix after + write out (coalesced across lanes per (j,g))
    #pragma unroll
    for (int j = 0; j < 4; j++) {
        int m = tid + j*256;
        float s[NHEAD];
        #pragma unroll
        for (int h = 0; h < NHEAD; h++) s[h] = sh[h*SHP + m];
        #pragma unroll
        for (int g = 0; g < NHEAD; g++) {
            float v = 0.f;
            #pragma unroll
            for (int h = 0; h < NHEAD; h++) v += tas[g*12 + h] * s[h];
            S[base + g*HS + m] = v;
        }
    }
}

// ---------------- depthwise conv1d over tokens, KS=7, pad 3 ----------------
__global__ void dwconv_kernel(const float* __restrict__ in, const float* __restrict__ w,
                              const float* __restrict__ bias, float* __restrict__ out)
{
    int idx = blockIdx.x * 256 + threadIdx.x;   // ROWS*CDIM total
    int c  = idx % CDIM;
    int bn = idx / CDIM;
    int n  = bn % NSEQ;
    int b  = bn / NSEQ;
    const float* xp = in + (long long)b*NSEQ*CDIM + c;
    float acc = bias[c];
    #pragma unroll
    for (int k = 0; k < 7; k++) {
        int m = n + k - 3;
        if (m >= 0 && m < NSEQ) acc += w[c*7 + k] * xp[(long long)m*CDIM];
    }
    out[idx] = acc;
}

// ---------------- launch ----------------
extern "C" void kernel_launch(void* const* d_in, const int* in_sizes, int n_in,
                              void* d_out, int out_size)
{
    const float* x       = (const float*)d_in[0];
    const float* w_qkv   = (const float*)d_in[1];
    const float* b_qkv   = (const float*)d_in[2];
    const float* w_proj  = (const float*)d_in[3];
    const float* b_proj  = (const float*)d_in[4];
    const float* w_fc1   = (const float*)d_in[5];
    const float* b_fc1   = (const float*)d_in[6];
    const float* w_fc2   = (const float*)d_in[7];
    const float* b_fc2   = (const float*)d_in[8];
    const float* t_before= (const float*)d_in[9];
    const float* t_after = (const float*)d_in[10];
    const float* g1      = (const float*)d_in[11];
    const float* be1     = (const float*)d_in[12];
    const float* g2      = (const float*)d_in[13];
    const float* be2     = (const float*)d_in[14];
    const float* dw_w    = (const float*)d_in[15];
    const float* dw_b    = (const float*)d_in[16];
    const float* gm      = (const float*)d_in[17];
    const float* bm      = (const float*)d_in[18];
    float* out = (float*)d_out;

    float *ph, *pqkv, *pS, *pattn, *px2, *ph2, *pconv, *pm, *pff;
    cudaGetSymbolAddress((void**)&ph,    g_h);
    cudaGetSymbolAddress((void**)&pqkv,  g_qkv);
    cudaGetSymbolAddress((void**)&pS,    g_S);
    cudaGetSymbolAddress((void**)&pattn, g_attn);
    cudaGetSymbolAddress((void**)&px2,   g_x2);
    cudaGetSymbolAddress((void**)&ph2,   g_h2);
    cudaGetSymbolAddress((void**)&pconv, g_conv);
    cudaGetSymbolAddress((void**)&pm,    g_m);
    cudaGetSymbolAddress((void**)&pff,   g_ff);

    const long long HS    = 1024LL*1024LL;     // per-head score stride
    const long long QKVB  = (long long)NSEQ * 3 * CDIM; // per-batch qkv stride

    // smem opt-in for mix-softmax (12*1025*4 = 49200 B > 48KB default)
    cudaFuncSetAttribute(mixsoftmax_kernel,
                         cudaFuncAttributeMaxDynamicSharedMemorySize, 12*SHP*4);

    // 1) LN1
    ln_kernel<<<ROWS, 256>>>(x, g1, be1, ph);

    // 2) QKV: [4096,2304] = h @ w_qkv^T + b_qkv
    gemm_kernel<128,128,8,8,8,true,1><<<dim3(18,32,1), 256>>>(
        ph, w_qkv, pqkv, ROWS, 3*CDIM, CDIM, CDIM, CDIM, 3*CDIM,
        0,0, 0,0, 0,0, 1, b_qkv, nullptr, 0, 1.0f);

    // 3) QK^T * scale, batched over (b,h): S[b,h] = Q K^T / 8
    gemm_kernel<128,128,8,8,8,true,0><<<dim3(8,8,BATCH*NHEAD), 256>>>(
        pqkv, pqkv + CDIM, pS, NSEQ, NSEQ, HDIM, 3*CDIM, 3*CDIM, NSEQ,
        QKVB, HDIM, QKVB, HDIM, (long long)NHEAD*HS, HS, NHEAD,
        nullptr, nullptr, 0, 0.125f);

    // 4) head-mix -> softmax -> head-mix, in place on S
    mixsoftmax_kernel<<<ROWS, 256, 12*SHP*4>>>(pS, t_before, t_after);

    // 5) AV (NN), batched over (b,h), write directly to [B,N,C]
    gemm_kernel<128,64,8,8,4,false,0><<<dim3(1,8,BATCH*NHEAD), 256>>>(
        pS, pqkv + 2*CDIM, pattn, NSEQ, HDIM, NSEQ, NSEQ, 3*CDIM, CDIM,
        (long long)NHEAD*HS, HS, QKVB, HDIM, (long long)NSEQ*CDIM, HDIM, NHEAD,
        nullptr, nullptr, 0, 1.0f);

    // 6) proj + bias + residual(x)
    gemm_kernel<128,128,8,8,8,true,3><<<dim3(6,32,1), 256>>>(
        pattn, w_proj, px2, ROWS, CDIM, CDIM, CDIM, CDIM, CDIM,
        0,0, 0,0, 0,0, 1, b_proj, x, CDIM, 1.0f);

    // 7) LN2
    ln_kernel<<<ROWS, 256>>>(px2, g2, be2, ph2);

    // 8) depthwise conv over tokens + bias
    dwconv_kernel<<<ROWS*CDIM/256, 256>>>(ph2, dw_w, dw_b, pconv);

    // 9) LN (gm, bm)
    ln_kernel<<<ROWS, 256>>>(pconv, gm, bm, pm);

    // 10) fc1 + bias + exact GELU
    gemm_kernel<128,128,8,8,8,true,2><<<dim3(24,32,1), 256>>>(
        pm, w_fc1, pff, ROWS, DFFN, CDIM, CDIM, CDIM, DFFN,
        0,0, 0,0, 0,0, 1, b_fc1, nullptr, 0, 1.0f);

    // 11) fc2 + bias + residual(x2) -> out
    gemm_kernel<128,128,8,8,8,true,3><<<dim3(6,32,1), 256>>>(
        pff, w_fc2, out, ROWS, CDIM, DFFN, DFFN, DFFN, CDIM,
        0,0, 0,0, 0,0, 1, b_fc2, px2, CDIM, 1.0f);
}

// round 2
// speedup vs baseline: 1.0062x; 1.0062x over previous
#include <cuda_runtime.h>
#include <math.h>

#define BATCH 4
#define NSEQ  1024
#define CDIM  768
#define NHEAD 12
#define HDIM  64
#define DFFN  3072
#define ROWS  (BATCH*NSEQ)   // 4096

// ---------------- scratch (static device globals; no allocation) ----------------
__device__ float g_h   [ROWS*CDIM];          // ln1 out
__device__ float g_qkv [ROWS*3*CDIM];        // qkv
__device__ float g_S   [50331648];           // 4*12*1024*1024 attention scores (reused for P)
__device__ float g_attn[ROWS*CDIM];          // AV out, [B,N,C]
__device__ float g_x2  [ROWS*CDIM];          // after proj + residual
__device__ float g_h2  [ROWS*CDIM];          // ln2 out
__device__ float g_conv[ROWS*CDIM];          // depthwise conv out
__device__ float g_m   [ROWS*CDIM];          // ln_m out
__device__ float g_ff  [ROWS*DFFN];          // fc1 out

// ---------------- generic tiled fp32 GEMM ----------------
// C[M,N] = alpha * A[M,K] * op(B) (+ bias[n]) (+gelu) (+ res[m,n])
// BT=true : B is [N,K] row-major (ldb = row stride)  -> C = A * B^T
// BT=false: B is [K,N] row-major (ldb = row stride)  -> C = A * B
// Batched: blockIdx.z = bi*inner + hi, offsets = bi*s? + hi*s?2
// EPI: 0 = scale only, 1 = +bias, 2 = +bias then exact GELU, 3 = +bias +res
template<int BM, int BN, int BK, int TM, int TN, bool BT, int EPI>
__global__ void __launch_bounds__(256)
gemm_kernel(const float* __restrict__ A, const float* __restrict__ B,
            float* __restrict__ C,
            int M, int N, int K,
            int lda, int ldb, int ldc,
            long long sA, long long sA2,
            long long sB, long long sB2,
            long long sC, long long sC2, int inner,
            const float* __restrict__ bias,
            const float* __restrict__ res, int ldres,
            float alpha)
{
    constexpr int THREADS = (BM/TM)*(BN/TN);
    __shared__ __align__(16) float As[BK][BM+4];
    __shared__ __align__(16) float Bs[BK][BN+4];

    int z  = blockIdx.z;
    int bi = z / inner;
    int hi = z - bi*inner;
    A += bi*sA + hi*sA2;
    B += bi*sB + hi*sB2;
    C += bi*sC + hi*sC2;

    const int m0  = blockIdx.y * BM;
    const int n0  = blockIdx.x * BN;
    const int tid = threadIdx.x;
    const int tx  = tid % (BN/TN);
    const int ty  = tid / (BN/TN);

    float acc[TM][TN];
    #pragma unroll
    for (int i = 0; i < TM; i++)
        #pragma unroll
        for (int j = 0; j < TN; j++) acc[i][j] = 0.f;

    for (int k0 = 0; k0 < K; k0 += BK) {
        // A tile: BM x BK, float4 along k
        #pragma unroll
        for (int idx = tid; idx < BM*BK/4; idx += THREADS) {
            int m  = idx / (BK/4);
            int kk = (idx - m*(BK/4)) * 4;
            float4 v = *(const float4*)(A + (long long)(m0+m)*lda + k0 + kk);
            As[kk+0][m] = v.x; As[kk+1][m] = v.y; As[kk+2][m] = v.z; As[kk+3][m] = v.w;
        }
        if (BT) {
            #pragma unroll
            for (int idx = tid; idx < BN*BK/4; idx += THREADS) {
                int n  = idx / (BK/4);
                int kk = (idx - n*(BK/4)) * 4;
                float4 v = *(const float4*)(B + (long long)(n0+n)*ldb + k0 + kk);
                Bs[kk+0][n] = v.x; Bs[kk+1][n] = v.y; Bs[kk+2][n] = v.z; Bs[kk+3][n] = v.w;
            }
        } else {
            #pragma unroll
            for (int idx = tid; idx < BK*BN/4; idx += THREADS) {
                int k  = idx / (BN/4);
                int nn = (idx - k*(BN/4)) * 4;
                float4 v = *(const float4*)(B + (long long)(k0+k)*ldb + n0 + nn);
                Bs[k][nn+0] = v.x; Bs[k][nn+1] = v.y; Bs[k][nn+2] = v.z; Bs[k][nn+3] = v.w;
            }
        }
        __syncthreads();

        #pragma unroll
        for (int k = 0; k < BK; k++) {
            float ra[TM], rb[TN];
            #pragma unroll
            for (int i = 0; i < TM; i += 4) {
                float4 t = *(const float4*)&As[k][ty*TM + i];
                ra[i] = t.x; ra[i+1] = t.y; ra[i+2] = t.z; ra[i+3] = t.w;
            }
            #pragma unroll
            for (int j = 0; j < TN; j += 4) {
                float4 t = *(const float4*)&Bs[k][tx*TN + j];
                rb[j] = t.x; rb[j+1] = t.y; rb[j+2] = t.z; rb[j+3] = t.w;
            }
            #pragma unroll
            for (int i = 0; i < TM; i++)
                #pragma unroll
                for (int j = 0; j < TN; j++)
                    acc[i][j] += ra[i] * rb[j];
        }
        __syncthreads();
    }

    #pragma unroll
    for (int i = 0; i < TM; i++) {
        int r = m0 + ty*TM + i;
        #pragma unroll
        for (int j = 0; j < TN; j++) {
            int c = n0 + tx*TN + j;
            float v = acc[i][j] * alpha;
            if (EPI >= 1) v += bias[c];
            if (EPI == 2) v = 0.5f * v * (1.0f + erff(v * 0.70710678118654752f));
            if (EPI == 3) v += res[(long long)r*ldres + c];
            C[(long long)r*ldc + c] = v;
        }
    }
}

// ---------------- LayerNorm (one block per row, C=768) ----------------
__global__ void ln_kernel(const float* __restrict__ in, const float* __restrict__ g,
                          const float* __restrict__ b, float* __restrict__ out)
{
    int row = blockIdx.x;
    const float* x = in + (long long)row * CDIM;
    float* o = out + (long long)row * CDIM;
    int tid = threadIdx.x;
    float xv[3];
    float s = 0.f, ss = 0.f;
    #pragma unroll
    for (int i = 0; i < 3; i++) {
        float v = x[tid + i*256];
        xv[i] = v; s += v; ss += v*v;
    }
    __shared__ float red[64];
    #pragma unroll
    for (int off = 16; off > 0; off >>= 1) {
        s  += __shfl_down_sync(0xffffffffu, s,  off);
        ss += __shfl_down_sync(0xffffffffu, ss, off);
    }
    int warp = tid >> 5, lane = tid & 31;
    if (lane == 0) { red[warp] = s; red[32+warp] = ss; }
    __syncthreads();
    if (warp == 0) {
        s  = (lane < 8) ? red[lane]    : 0.f;
        ss = (lane < 8) ? red[32+lane] : 0.f;
        #pragma unroll
        for (int off = 4; off > 0; off >>= 1) {
            s  += __shfl_down_sync(0xffffffffu, s,  off);
            ss += __shfl_down_sync(0xffffffffu, ss, off);
        }
        if (lane == 0) { red[0] = s; red[1] = ss; }
    }
    __syncthreads();
    float mu   = red[0] * (1.f/CDIM);
    float var  = red[1] * (1.f/CDIM) - mu*mu;
    float rstd = rsqrtf(var + 1e-5f);
    #pragma unroll
    for (int i = 0; i < 3; i++) {
        int c = tid + i*256;
        o[c] = (xv[i] - mu) * rstd * g[c] + b[c];
    }
}

// ---------------- head-mix -> softmax -> head-mix (in place on S) ----------------
// one block per (b,n); 12x1024 score slab in dynamic smem, stride 1025 (conflict-free cols)
#define SHP 1025
__global__ void mixsoftmax_kernel(float* __restrict__ S,
                                  const float* __restrict__ tb,
                                  const float* __restrict__ ta)
{
    extern __shared__ float sh[];                 // 12 * SHP floats
    __shared__ float tbs[144], tas[144];
    int bn = blockIdx.x;
    int b = bn >> 10, n = bn & 1023;
    int tid = threadIdx.x;
    if (tid < 144) { tbs[tid] = tb[tid]; tas[tid] = ta[tid]; }
    const long long HS = 1024LL*1024LL;
    long long base = ((long long)b*NHEAD*1024 + n) * 1024;
    #pragma unroll
    for (int h = 0; h < NHEAD; h++)
        for (int m = tid; m < 1024; m += 256)
            sh[h*SHP + m] = S[base + h*HS + m];
    __syncthreads();

    // mix before (column-owned, in place, race-free)
    #pragma unroll
    for (int j = 0; j < 4; j++) {
        int m = tid + j*256;
        float s[NHEAD], a[NHEAD];
        #pragma unroll
        for (int h = 0; h < NHEAD; h++) s[h] = sh[h*SHP + m];
        #pragma unroll
        for (int g = 0; g < NHEAD; g++) {
            float v = 0.f;
            #pragma unroll
            for (int h = 0; h < NHEAD; h++) v += tbs[g*12 + h] * s[h];
            a[g] = v;
        }
        #pragma unroll
        for (int g = 0; g < NHEAD; g++) sh[g*SHP + m] = a[g];
    }
    __syncthreads();

    // softmax per head row (warp per row)
    int warp = tid >> 5, lane = tid & 31;
    for (int h = warp; h < NHEAD; h += 8) {
        float* row = sh + h*SHP;
        float mx = -1e30f;
        for (int m = lane; m < 1024; m += 32) mx = fmaxf(mx, row[m]);
        #pragma unroll
        for (int off = 16; off > 0; off >>= 1) mx = fmaxf(mx, __shfl_xor_sync(0xffffffffu, mx, off));
        float sum = 0.f;
        for (int m = lane; m < 1024; m += 32) {
            float e = __expf(row[m] - mx);
            row[m] = e; sum += e;
        }
        #pragma unroll
        for (int off = 16; off > 0; off >>= 1) sum += __shfl_xor_sync(0xffffffffu, sum, off);
        float inv = 1.f / sum;
        for (int m = lane; m < 1024; m += 32) row[m] *= inv;
    }
    __syncthreads();

    // mix after + write out (coalesced across lanes per (j,g))
    #pragma unroll
    for (int j = 0; j < 4; j++) {
        int m = tid + j*256;
        float s[NHEAD];
        #pragma unroll
        for (int h = 0; h < NHEAD; h++) s[h] = sh[h*SHP + m];
        #pragma unroll
        for (int g = 0; g < NHEAD; g++) {
            float v = 0.f;
            #pragma unroll
            for (int h = 0; h < NHEAD; h++) v += tas[g*12 + h] * s[h];
            S[base + g*HS + m] = v;
        }
    }
}

// ---------------- depthwise conv1d over tokens, KS=7, pad 3 ----------------
__global__ void dwconv_kernel(const float* __restrict__ in, const float* __restrict__ w,
                              const float* __restrict__ bias, float* __restrict__ out)
{
    int idx = blockIdx.x * 256 + threadIdx.x;   // ROWS*CDIM total
    int c  = idx % CDIM;
    int bn = idx / CDIM;
    int n  = bn % NSEQ;
    int b  = bn / NSEQ;
    const float* xp = in + (long long)b*NSEQ*CDIM + c;
    float acc = bias[c];
    #pragma unroll
    for (int k = 0; k < 7; k++) {
        int m = n + k - 3;
        if (m >= 0 && m < NSEQ) acc += w[c*7 + k] * xp[(long long)m*CDIM];
    }
    out[idx] = acc;
}

// ---------------- launch ----------------
extern "C" void kernel_launch(void* const* d_in, const int* in_sizes, int n_in,
                              void* d_out, int out_size)
{
    const float* x       = (const float*)d_in[0];
    const float* w_qkv   = (const float*)d_in[1];
    const float* b_qkv   = (const float*)d_in[2];
    const float* w_proj  = (const float*)d_in[3];
    const float* b_proj  = (const float*)d_in[4];
    const float* w_fc1   = (const float*)d_in[5];
    const float* b_fc1   = (const float*)d_in[6];
    const float* w_fc2   = (const float*)d_in[7];
    const float* b_fc2   = (const float*)d_in[8];
    const float* t_before= (const float*)d_in[9];
    const float* t_after = (const float*)d_in[10];
    const float* g1      = (const float*)d_in[11];
    const float* be1     = (const float*)d_in[12];
    const float* g2      = (const float*)d_in[13];
    const float* be2     = (const float*)d_in[14];
    const float* dw_w    = (const float*)d_in[15];
    const float* dw_b    = (const float*)d_in[16];
    const float* gm      = (const float*)d_in[17];
    const float* bm      = (const float*)d_in[18];
    float* out = (float*)d_out;

    float *ph, *pqkv, *pS, *pattn, *px2, *ph2, *pconv, *pm, *pff;
    cudaGetSymbolAddress((void**)&ph,    g_h);
    cudaGetSymbolAddress((void**)&pqkv,  g_qkv);
    cudaGetSymbolAddress((void**)&pS,    g_S);
    cudaGetSymbolAddress((void**)&pattn, g_attn);
    cudaGetSymbolAddress((void**)&px2,   g_x2);
    cudaGetSymbolAddress((void**)&ph2,   g_h2);
    cudaGetSymbolAddress((void**)&pconv, g_conv);
    cudaGetSymbolAddress((void**)&pm,    g_m);
    cudaGetSymbolAddress((void**)&pff,   g_ff);

    const long long HS    = 1024LL*1024LL;     // per-head score stride
    const long long QKVB  = (long long)NSEQ * 3 * CDIM; // per-batch qkv stride

    // smem opt-in for mix-softmax (12*1025*4 = 49200 B > 48KB default)
    cudaFuncSetAttribute(mixsoftmax_kernel,
                         cudaFuncAttributeMaxDynamicSharedMemorySize, 12*SHP*4);

    // 1) LN1
    ln_kernel<<<ROWS, 256>>>(x, g1, be1, ph);

    // 2) QKV: [4096,2304] = h @ w_qkv^T + b_qkv
    gemm_kernel<128,128,8,8,8,true,1><<<dim3(18,32,1), 256>>>(
        ph, w_qkv, pqkv, ROWS, 3*CDIM, CDIM, CDIM, CDIM, 3*CDIM,
        0,0, 0,0, 0,0, 1, b_qkv, nullptr, 0, 1.0f);

    // 3) QK^T * scale, batched over (b,h): S[b,h] = Q K^T / 8
    gemm_kernel<128,128,8,8,8,true,0><<<dim3(8,8,BATCH*NHEAD), 256>>>(
        pqkv, pqkv + CDIM, pS, NSEQ, NSEQ, HDIM, 3*CDIM, 3*CDIM, NSEQ,
        QKVB, HDIM, QKVB, HDIM, (long long)NHEAD*HS, HS, NHEAD,
        nullptr, nullptr, 0, 0.125f);

    // 4) head-mix -> softmax -> head-mix, in place on S
    mixsoftmax_kernel<<<ROWS, 256, 12*SHP*4>>>(pS, t_before, t_after);

    // 5) AV (NN), batched over (b,h), write directly to [B,N,C]
    gemm_kernel<128,64,8,8,4,false,0><<<dim3(1,8,BATCH*NHEAD), 256>>>(
        pS, pqkv + 2*CDIM, pattn, NSEQ, HDIM, NSEQ, NSEQ, 3*CDIM, CDIM,
        (long long)NHEAD*HS, HS, QKVB, HDIM, (long long)NSEQ*CDIM, HDIM, NHEAD,
        nullptr, nullptr, 0, 1.0f);

    // 6) proj + bias + residual(x)
    gemm_kernel<128,128,8,8,8,true,3><<<dim3(6,32,1), 256>>>(
        pattn, w_proj, px2, ROWS, CDIM, CDIM, CDIM, CDIM, CDIM,
        0,0, 0,0, 0,0, 1, b_proj, x, CDIM, 1.0f);

    // 7) LN2
    ln_kernel<<<ROWS, 256>>>(px2, g2, be2, ph2);

    // 8) depthwise conv over tokens + bias
    dwconv_kernel<<<ROWS*CDIM/256, 256>>>(ph2, dw_w, dw_b, pconv);

    // 9) LN (gm, bm)
    ln_kernel<<<ROWS, 256>>>(pconv, gm, bm, pm);

    // 10) fc1 + bias + exact GELU
    gemm_kernel<128,128,8,8,8,true,2><<<dim3(24,32,1), 256>>>(
        pm, w_fc1, pff, ROWS, DFFN, CDIM, CDIM, CDIM, DFFN,
        0,0, 0,0, 0,0, 1, b_fc1, nullptr, 0, 1.0f);

    // 11) fc2 + bias + residual(x2) -> out
    gemm_kernel<128,128,8,8,8,true,3><<<dim3(6,32,1), 256>>>(
        pff, w_fc2, out, ROWS, CDIM, DFFN, DFFN, DFFN, CDIM,
        0,0, 0,0, 0,0, 1, b_fc2, px2, CDIM, 1.0f);
}

// round 4
// speedup vs baseline: 2.0374x; 2.0248x over previous
#include <cuda_runtime.h>
#include <cuda_bf16.h>
#include <math.h>
#include <stdint.h>
typedef __nv_bfloat16 bf16;

#define NHEAD 12
#define ROWS  4096
#define HSs   1048576LL
#define KOFF  3145728

// ---------------- scratch ----------------
__device__ __align__(16) float g_S  [50331648];
__device__ __align__(16) bf16  g_Phi[50331648], g_Plo[50331648];
__device__ __align__(16) bf16  g_qkh[6291456],  g_qkl[6291456];   // q then k, [B,H,N,64]
__device__ __align__(16) bf16  g_vh [3145728],  g_vl [3145728];   // [B,H,N,64]
__device__ __align__(16) bf16  g_hh [3145728],  g_hl [3145728];
__device__ __align__(16) bf16  g_ah [3145728],  g_al [3145728];
__device__ __align__(16) bf16  g_mh [3145728],  g_ml [3145728];
__device__ __align__(16) bf16  g_fh [12582912], g_fl [12582912];
__device__ __align__(16) float g_x2 [3145728], g_h2[3145728], g_cv[3145728];
__device__ __align__(16) bf16  g_w1h[1769472], g_w1l[1769472];
__device__ __align__(16) bf16  g_w2h[589824],  g_w2l[589824];
__device__ __align__(16) bf16  g_w3h[2359296], g_w3l[2359296];
__device__ __align__(16) bf16  g_w4h[2359296], g_w4l[2359296];

__device__ __forceinline__ uint32_t smem_u32(const void* p){
    uint32_t a; asm("{ .reg .u64 t; cvta.to.shared.u64 t, %1; cvt.u32.u64 %0, t; }":"=r"(a):"l"(p)); return a;
}
#define LDM4(r0,r1,r2,r3,ad) asm volatile("ldmatrix.sync.aligned.m8n8.x4.shared.b16 {%0,%1,%2,%3},[%4];" \
    : "=r"(r0),"=r"(r1),"=r"(r2),"=r"(r3):"r"(ad))
#define MMA(d,a,b) asm volatile( \
    "mma.sync.aligned.m16n8k16.row.col.f32.bf16.bf16.f32 {%0,%1,%2,%3},{%4,%5,%6,%7},{%8,%9},{%0,%1,%2,%3};" \
    : "+f"((d)[0]),"+f"((d)[1]),"+f"((d)[2]),"+f"((d)[3]) \
    : "r"((a)[0]),"r"((a)[1]),"r"((a)[2]),"r"((a)[3]),"r"((b)[0]),"r"((b)[1]))
#define CPA(dst,src) asm volatile("cp.async.cg.shared.global [%0],[%1],16;"::"r"(dst),"l"(src))
#define CPCOMMIT()   asm volatile("cp.async.commit_group;":::"memory")
#define CPWAIT0()    asm volatile("cp.async.wait_group 0;":::"memory")

__device__ __forceinline__ void hilo(float v, bf16&h, bf16&l){ h=__float2bfloat16(v); l=__float2bfloat16(v-__bfloat162float(h)); }
__device__ __forceinline__ void st_b2(bf16* p, bf16 a, bf16 b){
    __nv_bfloat162 t; t.x=a; t.y=b; *(__nv_bfloat162*)p = t;
}

struct GP {
    const bf16 *Ah,*Al,*Bh,*Bl;
    int K, lda, ldb;
    long long sAz, sBz, sOz;
    float alpha;
    const float *bias, *res;
    float *outf; int ldo;
    bf16 *ohi,*olo; int ldoh;
    bf16 *vhi,*vlo;
};

// C[M,N] = A[M,K] @ op(B), bf16 hi/lo split (3 products). BT: B is [N,K] k-contig; else [K,N].
// EPI: 0=alpha->f32 batched, 1=QKV scatter, 2=AV->[B,N,C] bf16, 3=bias+res f32, 4=bias+gelu bf16
template<int BN,int EPI,bool BT>
__global__ void __launch_bounds__(256) mma_gemm(GP p){
    constexpr int WARPS_N = BN/32;
    constexpr int WM = 128/(8/WARPS_N);
    constexpr int MT = WM/16;
    constexpr int PAD = 40;
    constexpr int ABYT = 128*PAD*2;
    constexpr int BBYT = BN*PAD*2;
    constexpr int STG  = 2*ABYT + 2*BBYT;

    extern __shared__ char dsm[];
    const uint32_t sb = smem_u32(dsm);
    const int tid=threadIdx.x, wid=tid>>5, lane=tid&31;
    const int z=blockIdx.z, m0=blockIdx.y*128, n0=blockIdx.x*BN;
    const int wm_=wid/WARPS_N, wn_=wid%WARPS_N;

    const bf16* Ah=p.Ah+(long long)z*p.sAz; const bf16* Al=p.Al+(long long)z*p.sAz;
    const bf16* Bh=p.Bh+(long long)z*p.sBz; const bf16* Bl=p.Bl+(long long)z*p.sBz;

    float acc[MT][4][4];
    #pragma unroll
    for(int i=0;i<MT;i++)
        #pragma unroll
        for(int j=0;j<4;j++)
            #pragma unroll
            for(int e=0;e<4;e++) acc[i][j][e]=0.f;

    auto load_stage=[&](int t,int s){
        const long long k0=(long long)t<<5;
        const uint32_t b0 = sb + s*STG;
        #pragma unroll
        for(int i=tid;i<512;i+=256){
            int row=i>>2, seg=i&3;
            uint32_t d = b0 + (row*PAD+seg*8)*2;
            long long g=(long long)(m0+row)*p.lda + k0 + seg*8;
            CPA(d, Ah+g); CPA(d+ABYT, Al+g);
        }
        if(BT){
            #pragma unroll
            for(int i=tid;i<BN*4;i+=256){
                int row=i>>2, seg=i&3;
                uint32_t d=b0+2*ABYT+(row*PAD+seg*8)*2;
                long long g=(long long)(n0+row)*p.ldb + k0 + seg*8;
                CPA(d, Bh+g); CPA(d+BBYT, Bl+g);
            }
        } else {
            bf16* sh_=(bf16*)(dsm + s*STG + 2*ABYT);
            bf16* sl_=(bf16*)(dsm + s*STG + 2*ABYT + BBYT);
            #pragma unroll
            for(int i=tid;i<BN*4;i+=256){
                int tt=i>>3, ds=i&7;
                long long g=(long long)(k0+tt)*p.ldb + n0 + ds*8;
                uint4 vh=*(const uint4*)(Bh+g), vl=*(const uint4*)(Bl+g);
                const bf16* eh=(const bf16*)&vh; const bf16* el=(const bf16*)&vl;
                #pragma unroll
                for(int e=0;e<8;e++){
                    sh_[(ds*8+e)*PAD+tt]=eh[e];
                    sl_[(ds*8+e)*PAD+tt]=el[e];
                }
            }
        }
        CPCOMMIT();
    };

    auto compute=[&](int s){
        const uint32_t bA=sb+s*STG, bAl=bA+ABYT, bB=bA+2*ABYT, bBl=bB+BBYT;
        #pragma unroll
        for(int kk=0;kk<32;kk+=16){
            uint32_t bh[4][2], bl[4][2];
            #pragma unroll
            for(int nt=0;nt<2;nt++){
                int row = wn_*32 + nt*16 + (lane&7) + ((lane>>4)&1)*8;
                int ko  = kk + ((lane>>3)&1)*8;
                uint32_t off=(uint32_t)(row*PAD+ko)*2;
                LDM4(bh[2*nt][0],bh[2*nt][1],bh[2*nt+1][0],bh[2*nt+1][1], bB+off);
                LDM4(bl[2*nt][0],bl[2*nt][1],bl[2*nt+1][0],bl[2*nt+1][1], bBl+off);
            }
            #pragma unroll
            for(int mi=0;mi<MT;mi++){
                int row = wm_*WM + mi*16 + (lane&7) + ((lane>>3)&1)*8;
                int ko  = kk + ((lane>>4)&1)*8;
                uint32_t off=(uint32_t)(row*PAD+ko)*2;
                uint32_t ah[4], al[4];
                LDM4(ah[0],ah[1],ah[2],ah[3], bA+off);
                LDM4(al[0],al[1],al[2],al[3], bAl+off);
                #pragma unroll
                for(int ni=0;ni<4;ni++){
                    MMA(acc[mi][ni],ah,bh[ni]);
                    MMA(acc[mi][ni],ah,bl[ni]);
                    MMA(acc[mi][ni],al,bh[ni]);
                }
            }
        }
    };

    const int T = p.K>>5;
    load_stage(0,0);
    for(int t=0;t<T;t++){
        CPWAIT0();
        __syncthreads();
        if(t+1<T) load_stage(t+1,(t+1)&1);
        compute(t&1);
        __syncthreads();
    }

    // -------- epilogue (register-direct) --------
    const int rb = m0 + wm_*WM, cbse = n0 + wn_*32;
    #pragma unroll
    for(int mi=0;mi<MT;mi++){
        #pragma unroll
        for(int ni=0;ni<4;ni++){
            #pragma unroll
            for(int half=0;half<2;half++){
                int r = rb + mi*16 + (lane>>2) + half*8;
                int c = cbse + ni*8 + (lane&3)*2;
                float v0=acc[mi][ni][half*2], v1=acc[mi][ni][half*2+1];
                if(EPI==0){
                    float2 o; o.x=v0*p.alpha; o.y=v1*p.alpha;
                    *(float2*)(p.outf + (long long)z*p.sOz + (long long)r*p.ldo + c) = o;
                } else if(EPI==1){
                    v0+=p.bias[c]; v1+=p.bias[c+1];
                    bf16 h0,l0,h1,l1; hilo(v0,h0,l0); hilo(v1,h1,l1);
                    int b=r>>10, n=r&1023;
                    bf16 *dh, *dl; int cc;
                    if(c<768){ dh=p.ohi; dl=p.olo; cc=c; }
                    else if(c<1536){ dh=p.ohi+KOFF; dl=p.olo+KOFF; cc=c-768; }
                    else { dh=p.vhi; dl=p.vlo; cc=c-1536; }
                    int hh=cc>>6, d=cc&63;
                    long long o=((long long)(b*12+hh)*1024+n)*64+d;
                    st_b2(dh+o,h0,h1); st_b2(dl+o,l0,l1);
                } else if(EPI==2){
                    bf16 h0,l0,h1,l1; hilo(v0,h0,l0); hilo(v1,h1,l1);
                    int b=z/12, hh=z-b*12;
                    long long o=(long long)(b*1024+r)*768 + hh*64 + c;
                    st_b2(p.ohi+o,h0,h1); st_b2(p.olo+o,l0,l1);
                } else if(EPI==3){
                    long long o=(long long)r*p.ldo + c;
                    float2 rr=*(const float2*)(p.res+o);
                    float2 ov; ov.x=v0+p.bias[c]+rr.x; ov.y=v1+p.bias[c+1]+rr.y;
                    *(float2*)(p.outf+o)=ov;
                } else if(EPI==4){
                    v0+=p.bias[c]; v1+=p.bias[c+1];
                    v0=0.5f*v0*(1.0f+erff(v0*0.70710678118654752f));
                    v1=0.5f*v1*(1.0f+erff(v1*0.70710678118654752f));
                    bf16 h0,l0,h1,l1; hilo(v0,h0,l0); hilo(v1,h1,l1);
                    long long o=(long long)r*p.ldoh + c;
                    st_b2(p.ohi+o,h0,h1); st_b2(p.olo+o,l0,l1);
                }
            }
        }
    }
}

// ---------------- LayerNorm ----------------
__global__ void ln_kernel(const float* __restrict__ in, const float* __restrict__ g,
                          const float* __restrict__ b, float* __restrict__ outf,
                          bf16* __restrict__ ohi, bf16* __restrict__ olo){
    int row=blockIdx.x, tid=threadIdx.x;
    const float* x = in + (long long)row*768;
    float xv[3], s=0.f, ss=0.f;
    #pragma unroll
    for(int i=0;i<3;i++){ float v=x[tid+i*256]; xv[i]=v; s+=v; ss+=v*v; }
    __shared__ float red[64];
    #pragma unroll
    for(int o=16;o>0;o>>=1){ s+=__shfl_down_sync(~0u,s,o); ss+=__shfl_down_sync(~0u,ss,o); }
    int warp=tid>>5, lane=tid&31;
    if(lane==0){ red[warp]=s; red[32+warp]=ss; }
    __syncthreads();
    if(warp==0){
        s=(lane<8)?red[lane]:0.f; ss=(lane<8)?red[32+lane]:0.f;
        #pragma unroll
        for(int o=4;o>0;o>>=1){ s+=__shfl_down_sync(~0u,s,o); ss+=__shfl_down_sync(~0u,ss,o); }
        if(lane==0){ red[0]=s; red[1]=ss; }
    }
    __syncthreads();
    float mu=red[0]*(1.f/768), var=red[1]*(1.f/768)-mu*mu, rstd=rsqrtf(var+1e-5f);
    #pragma unroll
    for(int i=0;i<3;i++){
        int c=tid+i*256;
        float v=(xv[i]-mu)*rstd*g[c]+b[c];
        long long o=(long long)row*768+c;
        if(outf) outf[o]=v;
        if(ohi){ bf16 h,l; hilo(v,h,l); ohi[o]=h; olo[o]=l; }
    }
}

// ---------------- streaming mix->softmax->mix ----------------
__global__ void __launch_bounds__(256) mixsoftmax(
    const float* __restrict__ S, bf16* __restrict__ Phi, bf16* __restrict__ Plo,
    const float* __restrict__ tb, const float* __restrict__ ta){
    __shared__ float tbs[144], tas[144], wmx[8][12], wsm[8][12], rmx[12], rin[12];
    int tid=threadIdx.x, warp=tid>>5, lane=tid&31;
    if(tid<144){ tbs[tid]=tb[tid]; tas[tid]=ta[tid]; }
    __syncthreads();
    int bn=blockIdx.x, b=bn>>10, n=bn&1023;
    long long base=((long long)b*NHEAD*1024+n)*1024;
    float mx[12], sm[12];
    #pragma unroll
    for(int g=0;g<12;g++){ mx[g]=-3.0e38f; sm[g]=0.f; }
    #pragma unroll 1
    for(int m=tid;m<1024;m+=256){
        float s[12];
        #pragma unroll
        for(int h=0;h<12;h++) s[h]=S[base+h*HSs+m];
        #pragma unroll
        for(int g=0;g<12;g++){
            float v=0.f;
            #pragma unroll
            for(int h=0;h<12;h++) v=fmaf(tbs[g*12+h],s[h],v);
            if(v>mx[g]){ sm[g]=sm[g]*__expf(mx[g]-v)+1.f; mx[g]=v; }
            else sm[g]+=__expf(v-mx[g]);
        }
    }
    #pragma unroll
    for(int o=16;o>0;o>>=1){
        #pragma unroll
        for(int g=0;g<12;g++){
            float om=__shfl_xor_sync(~0u,mx[g],o), os=__shfl_xor_sync(~0u,sm[g],o);
            float nm=fmaxf(mx[g],om);
            sm[g]=sm[g]*__expf(mx[g]-nm)+os*__expf(om-nm); mx[g]=nm;
        }
    }
    if(lane==0){
        #pragma unroll
        for(int g=0;g<12;g++){ wmx[warp][g]=mx[g]; wsm[warp][g]=sm[g]; } }
    __syncthreads();
    if(tid<12){
        float M=-3.0e38f;
        #pragma unroll
        for(int w=0;w<8;w++) M=fmaxf(M,wmx[w][tid]);
        float Sm=0.f;
        #pragma unroll
        for(int w=0;w<8;w++) Sm+=wsm[w][tid]*__expf(wmx[w][tid]-M);
        rmx[tid]=M; rin[tid]=1.f/Sm;
    }
    __syncthreads();
    float MX[12], RS[12];
    #pragma unroll
    for(int g=0;g<12;g++){ MX[g]=rmx[g]; RS[g]=rin[g]; }
    #pragma unroll 1
    for(int m=tid;m<1024;m+=256){
        float s[12], pv[12];
        #pragma unroll
        for(int h=0;h<12;h++) s[h]=S[base+h*HSs+m];
        #pragma unroll
        for(int g=0;g<12;g++){
            float v=0.f;
            #pragma unroll
            for(int h=0;h<12;h++) v=fmaf(tbs[g*12+h],s[h],v);
            pv[g]=__expf(v-MX[g])*RS[g];
        }
        #pragma unroll
        for(int g=0;g<12;g++){
            float v=0.f;
            #pragma unroll
            for(int h=0;h<12;h++) v=fmaf(tas[g*12+h],pv[h],v);
            bf16 hi,lo; hilo(v,hi,lo);
            Phi[base+g*HSs+m]=hi; Plo[base+g*HSs+m]=lo;
        }
    }
}

// ---------------- depthwise conv + convert ----------------
__global__ void dwconv_kernel(const float* __restrict__ in, const float* __restrict__ w,
                              const float* __restrict__ bias, float* __restrict__ out){
    int idx=blockIdx.x*256+threadIdx.x;
    int c=idx%768, bn=idx/768, n=bn&1023, b=bn>>10;
    const float* xp = in + (long long)b*1024*768 + c;
    float acc=bias[c];
    #pragma unroll
    for(int k=0;k<7;k++){
        int m=n+k-3;
        if(m>=0 && m<1024) acc+=w[c*7+k]*xp[(long long)m*768];
    }
    out[idx]=acc;
}
__global__ void f2hilo(const float* __restrict__ in, bf16* __restrict__ hi, bf16* __restrict__ lo, int n){
    int i=blockIdx.x*256+threadIdx.x;
    if(i<n){ bf16 h,l; hilo(in[i],h,l); hi[i]=h; lo[i]=l; }
}

// ---------------- launch ----------------
extern "C" void kernel_launch(void* const* d_in, const int* in_sizes, int n_in,
                              void* d_out, int out_size){
    const float *x=(const float*)d_in[0], *w_qkv=(const float*)d_in[1], *b_qkv=(const float*)d_in[2];
    const float *w_proj=(const float*)d_in[3], *b_proj=(const float*)d_in[4];
    const float *w_fc1=(const float*)d_in[5], *b_fc1=(const float*)d_in[6];
    const float *w_fc2=(const float*)d_in[7], *b_fc2=(const float*)d_in[8];
    const float *t_before=(const float*)d_in[9], *t_after=(const float*)d_in[10];
    const float *g1=(const float*)d_in[11], *be1=(const float*)d_in[12];
    const float *g2=(const float*)d_in[13], *be2=(const float*)d_in[14];
    const float *dw_w=(const float*)d_in[15], *dw_b=(const float*)d_in[16];
    const float *gm=(const float*)d_in[17], *bm=(const float*)d_in[18];
    float* out=(float*)d_out;

    float *pS,*px2,*ph2,*pcv; bf16 *pPh,*pPl,*pqkh,*pqkl,*pvh,*pvl,*phh,*phl,*pah,*pal,*pmh,*pml,*pfh,*pfl;
    bf16 *w1h,*w1l,*w2h,*w2l,*w3h,*w3l,*w4h,*w4l;
    cudaGetSymbolAddress((void**)&pS,g_S);   cudaGetSymbolAddress((void**)&px2,g_x2);
    cudaGetSymbolAddress((void**)&ph2,g_h2); cudaGetSymbolAddress((void**)&pcv,g_cv);
    cudaGetSymbolAddress((void**)&pPh,g_Phi);cudaGetSymbolAddress((void**)&pPl,g_Plo);
    cudaGetSymbolAddress((void**)&pqkh,g_qkh);cudaGetSymbolAddress((void**)&pqkl,g_qkl);
    cudaGetSymbolAddress((void**)&pvh,g_vh); cudaGetSymbolAddress((void**)&pvl,g_vl);
    cudaGetSymbolAddress((void**)&phh,g_hh); cudaGetSymbolAddress((void**)&phl,g_hl);
    cudaGetSymbolAddress((void**)&pah,g_ah); cudaGetSymbolAddress((void**)&pal,g_al);
    cudaGetSymbolAddress((void**)&pmh,g_mh); cudaGetSymbolAddress((void**)&pml,g_ml);
    cudaGetSymbolAddress((void**)&pfh,g_fh); cudaGetSymbolAddress((void**)&pfl,g_fl);
    cudaGetSymbolAddress((void**)&w1h,g_w1h);cudaGetSymbolAddress((void**)&w1l,g_w1l);
    cudaGetSymbolAddress((void**)&w2h,g_w2h);cudaGetSymbolAddress((void**)&w2l,g_w2l);
    cudaGetSymbolAddress((void**)&w3h,g_w3h);cudaGetSymbolAddress((void**)&w3l,g_w3l);
    cudaGetSymbolAddress((void**)&w4h,g_w4h);cudaGetSymbolAddress((void**)&w4l,g_w4l);

    const int S128 = 2*(2*128*40*2 + 2*128*40*2);   // 81920
    const int S64  = 2*(2*128*40*2 + 2*64*40*2);    // 61440
    cudaFuncSetAttribute(mma_gemm<128,0,true>,  cudaFuncAttributeMaxDynamicSharedMemorySize, S128);
    cudaFuncSetAttribute(mma_gemm<128,1,true>,  cudaFuncAttributeMaxDynamicSharedMemorySize, S128);
    cudaFuncSetAttribute(mma_gemm<64,2,false>,  cudaFuncAttributeMaxDynamicSharedMemorySize, S64);
    cudaFuncSetAttribute(mma_gemm<128,3,true>,  cudaFuncAttributeMaxDynamicSharedMemorySize, S128);
    cudaFuncSetAttribute(mma_gemm<128,4,true>,  cudaFuncAttributeMaxDynamicSharedMemorySize, S128);

    f2hilo<<<(1769472+255)/256,256>>>(w_qkv,w1h,w1l,1769472);
    f2hilo<<<(589824+255)/256,256>>>(w_proj,w2h,w2l,589824);
    f2hilo<<<(2359296+255)/256,256>>>(w_fc1,w3h,w3l,2359296);
    f2hilo<<<(2359296+255)/256,256>>>(w_fc2,w4h,w4l,2359296);

    ln_kernel<<<ROWS,256>>>(x,g1,be1,nullptr,phh,phl);

    GP p{};
    // QKV: [4096,2304] = h @ w_qkv^T, scatter q/k/v (+bias)
    p.Ah=phh; p.Al=phl; p.Bh=w1h; p.Bl=w1l; p.K=768; p.lda=768; p.ldb=768;
    p.bias=b_qkv; p.ohi=pqkh; p.olo=pqkl; p.vhi=pvh; p.vlo=pvl;
    mma_gemm<128,1,true><<<dim3(18,32,1),256,S128>>>(p);

    // QK^T per (b,h): S = QK^T * 0.125
    p=GP{}; p.Ah=pqkh; p.Al=pqkl; p.Bh=pqkh+KOFF; p.Bl=pqkl+KOFF;
    p.K=64; p.lda=64; p.ldb=64; p.sAz=65536; p.sBz=65536; p.sOz=HSs;
    p.outf=pS; p.ldo=1024; p.alpha=0.125f;
    mma_gemm<128,0,true><<<dim3(8,8,48),256,S128>>>(p);

    mixsoftmax<<<ROWS,256>>>(pS,pPh,pPl,t_before,t_after);

    // AV per (b,h): P[1024,1024] @ V[1024,64] -> attn[B,N,C] bf16
    p=GP{}; p.Ah=pPh; p.Al=pPl; p.Bh=pvh; p.Bl=pvl;
    p.K=1024; p.lda=1024; p.ldb=64; p.sAz=HSs; p.sBz=65536;
    p.ohi=pah; p.olo=pal;
    mma_gemm<64,2,false><<<dim3(1,8,48),256,S64>>>(p);

    // proj + bias + residual(x) -> x2 (fp32)
    p=GP{}; p.Ah=pah; p.Al=pal; p.Bh=w2h; p.Bl=w2l;
    p.K=768; p.lda=768; p.ldb=768; p.bias=b_proj; p.res=x; p.outf=px2; p.ldo=768;
    mma_gemm<128,3,true><<<dim3(6,32,1),256,S128>>>(p);

    ln_kernel<<<ROWS,256>>>(px2,g2,be2,ph2,nullptr,nullptr);
    dwconv_kernel<<<ROWS*768/256,256>>>(ph2,dw_w,dw_b,pcv);
    ln_kernel<<<ROWS,256>>>(pcv,gm,bm,nullptr,pmh,pml);

    // fc1 + bias + gelu -> bf16 hi/lo
    p=GP{}; p.Ah=pmh; p.Al=pml; p.Bh=w3h; p.Bl=w3l;
    p.K=768; p.lda=768; p.ldb=768; p.bias=b_fc1; p.ohi=pfh; p.olo=pfl; p.ldoh=3072;
    mma_gemm<128,4,true><<<dim3(24,32,1),256,S128>>>(p);

    // fc2 + bias + residual(x2) -> out
    p=GP{}; p.Ah=pfh; p.Al=pfl; p.Bh=w4h; p.Bl=w4l;
    p.K=3072; p.lda=3072; p.ldb=3072; p.bias=b_fc2; p.res=px2; p.outf=out; p.ldo=768;
    mma_gemm<128,3,true><<<dim3(6,32,1),256,S128>>>(p);
}

// round 5
// speedup vs baseline: 2.7410x; 1.3454x over previous
#include <cuda_runtime.h>
#include <cuda_bf16.h>
#include <math.h>
#include <stdint.h>
typedef __nv_bfloat16 bf16;

#define NHEAD 12
#define ROWS  4096
#define HSs   1048576LL
#define KOFF  3145728

// ---------------- scratch ----------------
__device__ __align__(16) float g_S  [50331648];
__device__ __align__(16) bf16  g_Phi[50331648];
__device__ __align__(16) bf16  g_qkh[6291456],  g_qkl[6291456];   // q then k, [B,H,N,64]
__device__ __align__(16) bf16  g_vh [3145728],  g_vl [3145728];   // [B,H,N,64]
__device__ __align__(16) bf16  g_hh [3145728],  g_hl [3145728];
__device__ __align__(16) bf16  g_ah [3145728],  g_al [3145728];
__device__ __align__(16) bf16  g_mh [3145728],  g_ml [3145728];
__device__ __align__(16) bf16  g_fh [12582912], g_fl [12582912];
__device__ __align__(16) float g_x2 [3145728], g_h2[3145728], g_cv[3145728];
__device__ __align__(16) bf16  g_w1h[1769472], g_w1l[1769472];
__device__ __align__(16) bf16  g_w2h[589824],  g_w2l[589824];
__device__ __align__(16) bf16  g_w3h[2359296], g_w3l[2359296];
__device__ __align__(16) bf16  g_w4h[2359296], g_w4l[2359296];

__device__ __forceinline__ uint32_t smem_u32(const void* p){
    uint32_t a; asm("{ .reg .u64 t; cvta.to.shared.u64 t, %1; cvt.u32.u64 %0, t; }":"=r"(a):"l"(p)); return a;
}
#define LDM4(r0,r1,r2,r3,ad) asm volatile("ldmatrix.sync.aligned.m8n8.x4.shared.b16 {%0,%1,%2,%3},[%4];" \
    : "=r"(r0),"=r"(r1),"=r"(r2),"=r"(r3):"r"(ad))
#define MMA(d,a,b) asm volatile( \
    "mma.sync.aligned.m16n8k16.row.col.f32.bf16.bf16.f32 {%0,%1,%2,%3},{%4,%5,%6,%7},{%8,%9},{%0,%1,%2,%3};" \
    : "+f"((d)[0]),"+f"((d)[1]),"+f"((d)[2]),"+f"((d)[3]) \
    : "r"((a)[0]),"r"((a)[1]),"r"((a)[2]),"r"((a)[3]),"r"((b)[0]),"r"((b)[1]))
#define CPA(dst,src) asm volatile("cp.async.cg.shared.global [%0],[%1],16;"::"r"(dst),"l"(src))
#define CPCOMMIT()   asm volatile("cp.async.commit_group;":::"memory")
#define CPWAIT0()    asm volatile("cp.async.wait_group 0;":::"memory")

__device__ __forceinline__ void hilo(float v, bf16&h, bf16&l){ h=__float2bfloat16(v); l=__float2bfloat16(v-__bfloat162float(h)); }
__device__ __forceinline__ void st_b2(bf16* p, bf16 a, bf16 b){
    __nv_bfloat162 t; t.x=a; t.y=b; *(__nv_bfloat162*)p = t;
}

struct GP {
    const bf16 *Ah,*Al,*Bh,*Bl;
    int K, lda, ldb;
    long long sAz, sBz, sOz;
    float alpha;
    const float *bias, *res;
    float *outf; int ldo;
    bf16 *ohi,*olo; int ldoh;
    bf16 *vhi,*vlo;
};

// C[M,N] = A[M,K] @ op(B), bf16 hi/lo split. BT: B is [N,K] k-contig; else [K,N].
// HASAL: A has a lo component (3 products); else 2 products (Ah*Bh + Ah*Bl).
// EPI: 0=alpha->f32 batched, 1=QKV scatter, 2=AV->[B,N,C] bf16, 3=bias+res f32, 4=bias+gelu bf16
template<int BN,int EPI,bool BT,bool HASAL>
__global__ void __launch_bounds__(256) mma_gemm(GP p){
    constexpr int WARPS_N = BN/32;
    constexpr int WM = 128/(8/WARPS_N);
    constexpr int MT = WM/16;
    constexpr int PAD = 40;
    constexpr int ABYT = 128*PAD*2;
    constexpr int BBYT = BN*PAD*2;
    constexpr int AOFF = ABYT*(HASAL?2:1);
    constexpr int STG  = AOFF + 2*BBYT;

    extern __shared__ char dsm[];
    const uint32_t sb = smem_u32(dsm);
    const int tid=threadIdx.x, wid=tid>>5, lane=tid&31;
    const int z=blockIdx.z, m0=blockIdx.y*128, n0=blockIdx.x*BN;
    const int wm_=wid/WARPS_N, wn_=wid%WARPS_N;

    const bf16* Ah=p.Ah+(long long)z*p.sAz; const bf16* Al=HASAL?(p.Al+(long long)z*p.sAz):nullptr;
    const bf16* Bh=p.Bh+(long long)z*p.sBz; const bf16* Bl=p.Bl+(long long)z*p.sBz;

    float acc[MT][4][4];
    #pragma unroll
    for(int i=0;i<MT;i++)
        #pragma unroll
        for(int j=0;j<4;j++)
            #pragma unroll
            for(int e=0;e<4;e++) acc[i][j][e]=0.f;

    auto load_stage=[&](int t,int s){
        const long long k0=(long long)t<<5;
        const uint32_t b0 = sb + s*STG;
        #pragma unroll
        for(int i=tid;i<512;i+=256){
            int row=i>>2, seg=i&3;
            uint32_t d = b0 + (row*PAD+seg*8)*2;
            long long g=(long long)(m0+row)*p.lda + k0 + seg*8;
            CPA(d, Ah+g);
            if(HASAL) CPA(d+ABYT, Al+g);
        }
        if(BT){
            #pragma unroll
            for(int i=tid;i<BN*4;i+=256){
                int row=i>>2, seg=i&3;
                uint32_t d=b0+AOFF+(row*PAD+seg*8)*2;
                long long g=(long long)(n0+row)*p.ldb + k0 + seg*8;
                CPA(d, Bh+g); CPA(d+BBYT, Bl+g);
            }
        } else {
            bf16* sh_=(bf16*)(dsm + s*STG + AOFF);
            bf16* sl_=(bf16*)(dsm + s*STG + AOFF + BBYT);
            #pragma unroll
            for(int i=tid;i<BN*4;i+=256){
                int tt=i>>3, ds=i&7;
                long long g=(long long)(k0+tt)*p.ldb + n0 + ds*8;
                uint4 vh=*(const uint4*)(Bh+g), vl=*(const uint4*)(Bl+g);
                const bf16* eh=(const bf16*)&vh; const bf16* el=(const bf16*)&vl;
                #pragma unroll
                for(int e=0;e<8;e++){
                    sh_[(ds*8+e)*PAD+tt]=eh[e];
                    sl_[(ds*8+e)*PAD+tt]=el[e];
                }
            }
        }
        CPCOMMIT();
    };

    auto compute=[&](int s){
        const uint32_t bA=sb+s*STG, bAl=bA+ABYT, bB=bA+AOFF, bBl=bB+BBYT;
        #pragma unroll
        for(int kk=0;kk<32;kk+=16){
            uint32_t bh[4][2], bl[4][2];
            #pragma unroll
            for(int nt=0;nt<2;nt++){
                int row = wn_*32 + nt*16 + (lane&7) + ((lane>>4)&1)*8;
                int ko  = kk + ((lane>>3)&1)*8;
                uint32_t off=(uint32_t)(row*PAD+ko)*2;
                LDM4(bh[2*nt][0],bh[2*nt][1],bh[2*nt+1][0],bh[2*nt+1][1], bB+off);
                LDM4(bl[2*nt][0],bl[2*nt][1],bl[2*nt+1][0],bl[2*nt+1][1], bBl+off);
            }
            #pragma unroll
            for(int mi=0;mi<MT;mi++){
                int row = wm_*WM + mi*16 + (lane&7) + ((lane>>3)&1)*8;
                int ko  = kk + ((lane>>4)&1)*8;
                uint32_t off=(uint32_t)(row*PAD+ko)*2;
                uint32_t ah[4], al[4];
                LDM4(ah[0],ah[1],ah[2],ah[3], bA+off);
                if(HASAL){ LDM4(al[0],al[1],al[2],al[3], bAl+off); }
                #pragma unroll
                for(int ni=0;ni<4;ni++){
                    MMA(acc[mi][ni],ah,bh[ni]);
                    MMA(acc[mi][ni],ah,bl[ni]);
                    if(HASAL) MMA(acc[mi][ni],al,bh[ni]);
                }
            }
        }
    };

    const int T = p.K>>5;
    load_stage(0,0);
    for(int t=0;t<T;t++){
        CPWAIT0();
        __syncthreads();
        if(t+1<T) load_stage(t+1,(t+1)&1);
        compute(t&1);
        __syncthreads();
    }

    // -------- epilogue --------
    const int rb = m0 + wm_*WM, cbse = n0 + wn_*32;
    #pragma unroll
    for(int mi=0;mi<MT;mi++){
        #pragma unroll
        for(int ni=0;ni<4;ni++){
            #pragma unroll
            for(int half=0;half<2;half++){
                int r = rb + mi*16 + (lane>>2) + half*8;
                int c = cbse + ni*8 + (lane&3)*2;
                float v0=acc[mi][ni][half*2], v1=acc[mi][ni][half*2+1];
                if(EPI==0){
                    float2 o; o.x=v0*p.alpha; o.y=v1*p.alpha;
                    *(float2*)(p.outf + (long long)z*p.sOz + (long long)r*p.ldo + c) = o;
                } else if(EPI==1){
                    v0+=p.bias[c]; v1+=p.bias[c+1];
                    bf16 h0,l0,h1,l1; hilo(v0,h0,l0); hilo(v1,h1,l1);
                    int b=r>>10, n=r&1023;
                    bf16 *dh, *dl; int cc;
                    if(c<768){ dh=p.ohi; dl=p.olo; cc=c; }
                    else if(c<1536){ dh=p.ohi+KOFF; dl=p.olo+KOFF; cc=c-768; }
                    else { dh=p.vhi; dl=p.vlo; cc=c-1536; }
                    int hh=cc>>6, d=cc&63;
                    long long o=((long long)(b*12+hh)*1024+n)*64+d;
                    st_b2(dh+o,h0,h1); st_b2(dl+o,l0,l1);
                } else if(EPI==2){
                    bf16 h0,l0,h1,l1; hilo(v0,h0,l0); hilo(v1,h1,l1);
                    int b=z/12, hh=z-b*12;
                    long long o=(long long)(b*1024+r)*768 + hh*64 + c;
                    st_b2(p.ohi+o,h0,h1); st_b2(p.olo+o,l0,l1);
                } else if(EPI==3){
                    long long o=(long long)r*p.ldo + c;
                    float2 rr=*(const float2*)(p.res+o);
                    float2 ov; ov.x=v0+p.bias[c]+rr.x; ov.y=v1+p.bias[c+1]+rr.y;
                    *(float2*)(p.outf+o)=ov;
                } else if(EPI==4){
                    v0+=p.bias[c]; v1+=p.bias[c+1];
                    v0=0.5f*v0*(1.0f+erff(v0*0.70710678118654752f));
                    v1=0.5f*v1*(1.0f+erff(v1*0.70710678118654752f));
                    bf16 h0,l0,h1,l1; hilo(v0,h0,l0); hilo(v1,h1,l1);
                    long long o=(long long)r*p.ldoh + c;
                    st_b2(p.ohi+o,h0,h1); st_b2(p.olo+o,l0,l1);
                }
            }
        }
    }
}

// ---------------- LayerNorm ----------------
__global__ void ln_kernel(const float* __restrict__ in, const float* __restrict__ g,
                          const float* __restrict__ b, float* __restrict__ outf,
                          bf16* __restrict__ ohi, bf16* __restrict__ olo){
    int row=blockIdx.x, tid=threadIdx.x;
    const float* x = in + (long long)row*768;
    float xv[3], s=0.f, ss=0.f;
    #pragma unroll
    for(int i=0;i<3;i++){ float v=x[tid+i*256]; xv[i]=v; s+=v; ss+=v*v; }
    __shared__ float red[64];
    #pragma unroll
    for(int o=16;o>0;o>>=1){ s+=__shfl_down_sync(~0u,s,o); ss+=__shfl_down_sync(~0u,ss,o); }
    int warp=tid>>5, lane=tid&31;
    if(lane==0){ red[warp]=s; red[32+warp]=ss; }
    __syncthreads();
    if(warp==0){
        s=(lane<8)?red[lane]:0.f; ss=(lane<8)?red[32+lane]:0.f;
        #pragma unroll
        for(int o=4;o>0;o>>=1){ s+=__shfl_down_sync(~0u,s,o); ss+=__shfl_down_sync(~0u,ss,o); }
        if(lane==0){ red[0]=s; red[1]=ss; }
    }
    __syncthreads();
    float mu=red[0]*(1.f/768), var=red[1]*(1.f/768)-mu*mu, rstd=rsqrtf(var+1e-5f);
    #pragma unroll
    for(int i=0;i<3;i++){
        int c=tid+i*256;
        float v=(xv[i]-mu)*rstd*g[c]+b[c];
        long long o=(long long)row*768+c;
        if(outf) outf[o]=v;
        if(ohi){ bf16 h,l; hilo(v,h,l); ohi[o]=h; olo[o]=l; }
    }
}

// ---------------- fused mix->softmax->mix, single global pass, smem slab ----------------
// scores are tiny (|S|<~5) so exp needs no max subtraction (identical math to softmax).
#define MSP 1024
__global__ void __launch_bounds__(256) mixsoftmax(
    const float* __restrict__ S, bf16* __restrict__ Phi,
    const float* __restrict__ tb, const float* __restrict__ ta){
    extern __shared__ float sh[];                    // 12*MSP e-values
    __shared__ float tbs[144], tas[144], wsum[8][12], rin[12];
    int tid=threadIdx.x, warp=tid>>5, lane=tid&31;
    if(tid<144){ tbs[tid]=tb[tid]; tas[tid]=ta[tid]; }
    __syncthreads();
    int bn=blockIdx.x, b=bn>>10, n=bn&1023;
    long long base=((long long)b*NHEAD*1024+n)*1024;
    float sm[12];
    #pragma unroll
    for(int g=0;g<12;g++) sm[g]=0.f;
    #pragma unroll 1
    for(int j=0;j<4;j++){
        int m=tid+j*256;
        float s[12];
        #pragma unroll
        for(int h=0;h<12;h++) s[h]=S[base+h*HSs+m];
        #pragma unroll
        for(int g=0;g<12;g++){
            float v=0.f;
            #pragma unroll
            for(int h=0;h<12;h++) v=fmaf(tbs[g*12+h],s[h],v);
            float e=__expf(v);
            sh[g*MSP+m]=e; sm[g]+=e;
        }
    }
    #pragma unroll
    for(int o=16;o>0;o>>=1){
        #pragma unroll
        for(int g=0;g<12;g++) sm[g]+=__shfl_xor_sync(~0u,sm[g],o);
    }
    if(lane==0){
        #pragma unroll
        for(int g=0;g<12;g++) wsum[warp][g]=sm[g];
    }
    __syncthreads();
    if(tid<12){
        float t=0.f;
        #pragma unroll
        for(int w=0;w<8;w++) t+=wsum[w][tid];
        rin[tid]=1.f/t;
    }
    __syncthreads();
    float RS[12];
    #pragma unroll
    for(int g=0;g<12;g++) RS[g]=rin[g];
    #pragma unroll 1
    for(int j=0;j<4;j++){
        int m=tid+j*256;
        float e[12];
        #pragma unroll
        for(int h=0;h<12;h++) e[h]=sh[h*MSP+m]*RS[h];
        #pragma unroll
        for(int g=0;g<12;g++){
            float v=0.f;
            #pragma unroll
            for(int h=0;h<12;h++) v=fmaf(tas[g*12+h],e[h],v);
            Phi[base+g*HSs+m]=__float2bfloat16(v);
        }
    }
}

// ---------------- depthwise conv + convert ----------------
__global__ void dwconv_kernel(const float* __restrict__ in, const float* __restrict__ w,
                              const float* __restrict__ bias, float* __restrict__ out){
    int idx=blockIdx.x*256+threadIdx.x;
    int c=idx%768, bn=idx/768, n=bn&1023, b=bn>>10;
    const float* xp = in + (long long)b*1024*768 + c;
    float acc=bias[c];
    #pragma unroll
    for(int k=0;k<7;k++){
        int m=n+k-3;
        if(m>=0 && m<1024) acc+=w[c*7+k]*xp[(long long)m*768];
    }
    out[idx]=acc;
}
__global__ void f2hilo(const float* __restrict__ in, bf16* __restrict__ hi, bf16* __restrict__ lo, int n){
    int i=blockIdx.x*256+threadIdx.x;
    if(i<n){ bf16 h,l; hilo(in[i],h,l); hi[i]=h; lo[i]=l; }
}

// ---------------- launch ----------------
extern "C" void kernel_launch(void* const* d_in, const int* in_sizes, int n_in,
                              void* d_out, int out_size){
    const float *x=(const float*)d_in[0], *w_qkv=(const float*)d_in[1], *b_qkv=(const float*)d_in[2];
    const float *w_proj=(const float*)d_in[3], *b_proj=(const float*)d_in[4];
    const float *w_fc1=(const float*)d_in[5], *b_fc1=(const float*)d_in[6];
    const float *w_fc2=(const float*)d_in[7], *b_fc2=(const float*)d_in[8];
    const float *t_before=(const float*)d_in[9], *t_after=(const float*)d_in[10];
    const float *g1=(const float*)d_in[11], *be1=(const float*)d_in[12];
    const float *g2=(const float*)d_in[13], *be2=(const float*)d_in[14];
    const float *dw_w=(const float*)d_in[15], *dw_b=(const float*)d_in[16];
    const float *gm=(const float*)d_in[17], *bm=(const float*)d_in[18];
    float* out=(float*)d_out;

    float *pS,*px2,*ph2,*pcv; bf16 *pPh,*pqkh,*pqkl,*pvh,*pvl,*phh,*phl,*pah,*pal,*pmh,*pml,*pfh,*pfl;
    bf16 *w1h,*w1l,*w2h,*w2l,*w3h,*w3l,*w4h,*w4l;
    cudaGetSymbolAddress((void**)&pS,g_S);   cudaGetSymbolAddress((void**)&px2,g_x2);
    cudaGetSymbolAddress((void**)&ph2,g_h2); cudaGetSymbolAddress((void**)&pcv,g_cv);
    cudaGetSymbolAddress((void**)&pPh,g_Phi);
    cudaGetSymbolAddress((void**)&pqkh,g_qkh);cudaGetSymbolAddress((void**)&pqkl,g_qkl);
    cudaGetSymbolAddress((void**)&pvh,g_vh); cudaGetSymbolAddress((void**)&pvl,g_vl);
    cudaGetSymbolAddress((void**)&phh,g_hh); cudaGetSymbolAddress((void**)&phl,g_hl);
    cudaGetSymbolAddress((void**)&pah,g_ah); cudaGetSymbolAddress((void**)&pal,g_al);
    cudaGetSymbolAddress((void**)&pmh,g_mh); cudaGetSymbolAddress((void**)&pml,g_ml);
    cudaGetSymbolAddress((void**)&pfh,g_fh); cudaGetSymbolAddress((void**)&pfl,g_fl);
    cudaGetSymbolAddress((void**)&w1h,g_w1h);cudaGetSymbolAddress((void**)&w1l,g_w1l);
    cudaGetSymbolAddress((void**)&w2h,g_w2h);cudaGetSymbolAddress((void**)&w2l,g_w2l);
    cudaGetSymbolAddress((void**)&w3h,g_w3h);cudaGetSymbolAddress((void**)&w3l,g_w3l);
    cudaGetSymbolAddress((void**)&w4h,g_w4h);cudaGetSymbolAddress((void**)&w4l,g_w4l);

    const int S128 = 2*(2*128*40*2 + 2*128*40*2);   // 81920 (hi/lo A + hi/lo B)
    const int S64AV= 2*(1*128*40*2 + 2*64*40*2);    // 30720 (hi A only + hi/lo B)
    const int SMIX = 12*MSP*4;                       // 49152
    cudaFuncSetAttribute(mma_gemm<128,0,true,true>,  cudaFuncAttributeMaxDynamicSharedMemorySize, S128);
    cudaFuncSetAttribute(mma_gemm<128,1,true,true>,  cudaFuncAttributeMaxDynamicSharedMemorySize, S128);
    cudaFuncSetAttribute(mma_gemm<64,2,false,false>, cudaFuncAttributeMaxDynamicSharedMemorySize, S64AV);
    cudaFuncSetAttribute(mma_gemm<128,3,true,true>,  cudaFuncAttributeMaxDynamicSharedMemorySize, S128);
    cudaFuncSetAttribute(mma_gemm<128,4,true,true>,  cudaFuncAttributeMaxDynamicSharedMemorySize, S128);
    cudaFuncSetAttribute(mixsoftmax, cudaFuncAttributeMaxDynamicSharedMemorySize, SMIX);

    f2hilo<<<(1769472+255)/256,256>>>(w_qkv,w1h,w1l,1769472);
    f2hilo<<<(589824+255)/256,256>>>(w_proj,w2h,w2l,589824);
    f2hilo<<<(2359296+255)/256,256>>>(w_fc1,w3h,w3l,2359296);
    f2hilo<<<(2359296+255)/256,256>>>(w_fc2,w4h,w4l,2359296);

    ln_kernel<<<ROWS,256>>>(x,g1,be1,nullptr,phh,phl);

    GP p{};
    // QKV
    p.Ah=phh; p.Al=phl; p.Bh=w1h; p.Bl=w1l; p.K=768; p.lda=768; p.ldb=768;
    p.bias=b_qkv; p.ohi=pqkh; p.olo=pqkl; p.vhi=pvh; p.vlo=pvl;
    mma_gemm<128,1,true,true><<<dim3(18,32,1),256,S128>>>(p);

    // QK^T per (b,h): S = QK^T * 0.125
    p=GP{}; p.Ah=pqkh; p.Al=pqkl; p.Bh=pqkh+KOFF; p.Bl=pqkl+KOFF;
    p.K=64; p.lda=64; p.ldb=64; p.sAz=65536; p.sBz=65536; p.sOz=HSs;
    p.outf=pS; p.ldo=1024; p.alpha=0.125f;
    mma_gemm<128,0,true,true><<<dim3(8,8,48),256,S128>>>(p);

    mixsoftmax<<<ROWS,256,SMIX>>>(pS,pPh,t_before,t_after);

    // AV per (b,h): P[1024,1024](bf16) @ V[1024,64](hi/lo) -> attn[B,N,C]
    p=GP{}; p.Ah=pPh; p.Al=nullptr; p.Bh=pvh; p.Bl=pvl;
    p.K=1024; p.lda=1024; p.ldb=64; p.sAz=HSs; p.sBz=65536;
    p.ohi=pah; p.olo=pal;
    mma_gemm<64,2,false,false><<<dim3(1,8,48),256,S64AV>>>(p);

    // proj + bias + residual(x) -> x2
    p=GP{}; p.Ah=pah; p.Al=pal; p.Bh=w2h; p.Bl=w2l;
    p.K=768; p.lda=768; p.ldb=768; p.bias=b_proj; p.res=x; p.outf=px2; p.ldo=768;
    mma_gemm<128,3,true,true><<<dim3(6,32,1),256,S128>>>(p);

    ln_kernel<<<ROWS,256>>>(px2,g2,be2,ph2,nullptr,nullptr);
    dwconv_kernel<<<ROWS*768/256,256>>>(ph2,dw_w,dw_b,pcv);
    ln_kernel<<<ROWS,256>>>(pcv,gm,bm,nullptr,pmh,pml);

    // fc1 + bias + gelu
    p=GP{}; p.Ah=pmh; p.Al=pml; p.Bh=w3h; p.Bl=w3l;
    p.K=768; p.lda=768; p.ldb=768; p.bias=b_fc1; p.ohi=pfh; p.olo=pfl; p.ldoh=3072;
    mma_gemm<128,4,true,true><<<dim3(24,32,1),256,S128>>>(p);

    // fc2 + bias + residual(x2) -> out
    p=GP{}; p.Ah=pfh; p.Al=pfl; p.Bh=w4h; p.Bl=w4l;
    p.K=3072; p.lda=3072; p.ldb=3072; p.bias=b_fc2; p.res=px2; p.outf=out; p.ldo=768;
    mma_gemm<128,3,true,true><<<dim3(6,32,1),256,S128>>>(p);
}

// round 6
// speedup vs baseline: 3.3276x; 1.2140x over previous
#include <cuda_runtime.h>
#include <cuda_fp16.h>
#include <math.h>
#include <stdint.h>
typedef __half hf;

#define NHEAD 12
#define ROWS  4096
#define HSs   1048576LL

// ---------------- scratch ----------------
__device__ __align__(16) float g_S  [50331648];
__device__ __align__(16) hf    g_P  [50331648];
__device__ __align__(16) hf    g_q  [3145728];                    // [B,H,N,64] fp16
__device__ __align__(16) hf    g_kh [3145728], g_kl [3145728];    // [B,H,N,64] hi/lo
__device__ __align__(16) hf    g_vh [3145728], g_vl [3145728];    // [B,H,N,64] hi/lo
__device__ __align__(16) hf    g_h1 [3145728];                    // ln1 out fp16
__device__ __align__(16) hf    g_a  [3145728];                    // attn out [B*N,768]
__device__ __align__(16) hf    g_m  [3145728];                    // ln_m out
__device__ __align__(16) hf    g_f  [12582912];                   // fc1+gelu out
__device__ __align__(16) float g_x2 [3145728], g_h2[3145728], g_cv[3145728];
__device__ __align__(16) hf    g_w1h[1769472], g_w1l[1769472];
__device__ __align__(16) hf    g_w2h[589824],  g_w2l[589824];
__device__ __align__(16) hf    g_w3h[2359296], g_w3l[2359296];
__device__ __align__(16) hf    g_w4h[2359296], g_w4l[2359296];

__device__ __forceinline__ uint32_t smem_u32(const void* p){
    uint32_t a; asm("{ .reg .u64 t; cvta.to.shared.u64 t, %1; cvt.u32.u64 %0, t; }":"=r"(a):"l"(p)); return a;
}
#define LDM4(r0,r1,r2,r3,ad) asm volatile("ldmatrix.sync.aligned.m8n8.x4.shared.b16 {%0,%1,%2,%3},[%4];" \
    : "=r"(r0),"=r"(r1),"=r"(r2),"=r"(r3):"r"(ad))
#define MMA(d,a,b) asm volatile( \
    "mma.sync.aligned.m16n8k16.row.col.f32.f16.f16.f32 {%0,%1,%2,%3},{%4,%5,%6,%7},{%8,%9},{%0,%1,%2,%3};" \
    : "+f"((d)[0]),"+f"((d)[1]),"+f"((d)[2]),"+f"((d)[3]) \
    : "r"((a)[0]),"r"((a)[1]),"r"((a)[2]),"r"((a)[3]),"r"((b)[0]),"r"((b)[1]))
#define CPA(dst,src) asm volatile("cp.async.cg.shared.global [%0],[%1],16;"::"r"(dst),"l"(src))
#define CPCOMMIT()   asm volatile("cp.async.commit_group;":::"memory")
#define CPWAIT0()    asm volatile("cp.async.wait_group 0;":::"memory")

__device__ __forceinline__ void hilo(float v, hf&h, hf&l){
    h=__float2half_rn(v); l=__float2half_rn(v-__half2float(h));
}
__device__ __forceinline__ void st_h2(hf* p, hf a, hf b){
    __half2 t; t.x=a; t.y=b; *(__half2*)p = t;
}

struct GP {
    const hf *Ah,*Bh,*Bl;
    int K, lda, ldb;
    long long sAz, sBz, sOz;
    float alpha;
    const float *bias, *res;
    float *outf; int ldo;
    hf *o1; int ldoh;          // single-fp16 out (EPI 2/4) or Q (EPI 1)
    hf *kh,*kl,*vh,*vl;        // EPI 1 targets
};

// C[M,N] = A[M,K] @ op(B): A single fp16, B fp16 hi/lo (2 MMA products).
// BT: B is [N,K] k-contig; else [K,N].
// EPI: 0=alpha->f32 batched, 1=QKV scatter, 2=AV->[B,N,C] fp16, 3=bias+res f32, 4=bias+gelu fp16
template<int BN,int EPI,bool BT>
__global__ void __launch_bounds__(256) mma_gemm(GP p){
    constexpr int WARPS_N = BN/32;
    constexpr int WM = 128/(8/WARPS_N);
    constexpr int MT = WM/16;
    constexpr int PAD = 40;
    constexpr int ABYT = 128*PAD*2;
    constexpr int BBYT = BN*PAD*2;
    constexpr int STG  = ABYT + 2*BBYT;

    extern __shared__ char dsm[];
    const uint32_t sb = smem_u32(dsm);
    const int tid=threadIdx.x, wid=tid>>5, lane=tid&31;
    const int z=blockIdx.z, m0=blockIdx.y*128, n0=blockIdx.x*BN;
    const int wm_=wid/WARPS_N, wn_=wid%WARPS_N;

    const hf* Ah=p.Ah+(long long)z*p.sAz;
    const hf* Bh=p.Bh+(long long)z*p.sBz;
    const hf* Bl=p.Bl+(long long)z*p.sBz;

    float acc[MT][4][4];
    #pragma unroll
    for(int i=0;i<MT;i++)
        #pragma unroll
        for(int j=0;j<4;j++)
            #pragma unroll
            for(int e=0;e<4;e++) acc[i][j][e]=0.f;

    auto load_stage=[&](int t,int s){
        const long long k0=(long long)t<<5;
        const uint32_t b0 = sb + s*STG;
        #pragma unroll
        for(int i=tid;i<512;i+=256){
            int row=i>>2, seg=i&3;
            uint32_t d = b0 + (row*PAD+seg*8)*2;
            long long g=(long long)(m0+row)*p.lda + k0 + seg*8;
            CPA(d, Ah+g);
        }
        if(BT){
            #pragma unroll
            for(int i=tid;i<BN*4;i+=256){
                int row=i>>2, seg=i&3;
                uint32_t d=b0+ABYT+(row*PAD+seg*8)*2;
                long long g=(long long)(n0+row)*p.ldb + k0 + seg*8;
                CPA(d, Bh+g); CPA(d+BBYT, Bl+g);
            }
        } else {
            hf* sh_=(hf*)(dsm + s*STG + ABYT);
            hf* sl_=(hf*)(dsm + s*STG + ABYT + BBYT);
            #pragma unroll
            for(int i=tid;i<BN*4;i+=256){
                int tt=i>>3, ds=i&7;
                long long g=(long long)(k0+tt)*p.ldb + n0 + ds*8;
                uint4 vh=*(const uint4*)(Bh+g), vl=*(const uint4*)(Bl+g);
                const hf* eh=(const hf*)&vh; const hf* el=(const hf*)&vl;
                #pragma unroll
                for(int e=0;e<8;e++){
                    sh_[(ds*8+e)*PAD+tt]=eh[e];
                    sl_[(ds*8+e)*PAD+tt]=el[e];
                }
            }
        }
        CPCOMMIT();
    };

    auto compute=[&](int s){
        const uint32_t bA=sb+s*STG, bB=bA+ABYT, bBl=bB+BBYT;
        #pragma unroll
        for(int kk=0;kk<32;kk+=16){
            uint32_t bh[4][2], bl[4][2];
            #pragma unroll
            for(int nt=0;nt<2;nt++){
                int row = wn_*32 + nt*16 + (lane&7) + ((lane>>4)&1)*8;
                int ko  = kk + ((lane>>3)&1)*8;
                uint32_t off=(uint32_t)(row*PAD+ko)*2;
                LDM4(bh[2*nt][0],bh[2*nt][1],bh[2*nt+1][0],bh[2*nt+1][1], bB+off);
                LDM4(bl[2*nt][0],bl[2*nt][1],bl[2*nt+1][0],bl[2*nt+1][1], bBl+off);
            }
            #pragma unroll
            for(int mi=0;mi<MT;mi++){
                int row = wm_*WM + mi*16 + (lane&7) + ((lane>>3)&1)*8;
                int ko  = kk + ((lane>>4)&1)*8;
                uint32_t off=(uint32_t)(row*PAD+ko)*2;
                uint32_t ah[4];
                LDM4(ah[0],ah[1],ah[2],ah[3], bA+off);
                #pragma unroll
                for(int ni=0;ni<4;ni++){
                    MMA(acc[mi][ni],ah,bh[ni]);
                    MMA(acc[mi][ni],ah,bl[ni]);
                }
            }
        }
    };

    const int T = p.K>>5;
    load_stage(0,0);
    for(int t=0;t<T;t++){
        CPWAIT0();
        __syncthreads();
        if(t+1<T) load_stage(t+1,(t+1)&1);
        compute(t&1);
        __syncthreads();
    }

    // -------- epilogue --------
    const int rb = m0 + wm_*WM, cbse = n0 + wn_*32;
    #pragma unroll
    for(int mi=0;mi<MT;mi++){
        #pragma unroll
        for(int ni=0;ni<4;ni++){
            #pragma unroll
            for(int half=0;half<2;half++){
                int r = rb + mi*16 + (lane>>2) + half*8;
                int c = cbse + ni*8 + (lane&3)*2;
                float v0=acc[mi][ni][half*2], v1=acc[mi][ni][half*2+1];
                if(EPI==0){
                    float2 o; o.x=v0*p.alpha; o.y=v1*p.alpha;
                    *(float2*)(p.outf + (long long)z*p.sOz + (long long)r*p.ldo + c) = o;
                } else if(EPI==1){
                    v0+=p.bias[c]; v1+=p.bias[c+1];
                    int b=r>>10, n=r&1023;
                    if(c<768){
                        int hh=c>>6, d=c&63;
                        long long o=((long long)(b*12+hh)*1024+n)*64+d;
                        st_h2(p.o1+o, __float2half_rn(v0), __float2half_rn(v1));
                    } else {
                        int cc=(c<1536)?(c-768):(c-1536);
                        hf* dh=(c<1536)?p.kh:p.vh; hf* dl=(c<1536)?p.kl:p.vl;
                        int hh=cc>>6, d=cc&63;
                        long long o=((long long)(b*12+hh)*1024+n)*64+d;
                        hf h0,l0,h1,l1; hilo(v0,h0,l0); hilo(v1,h1,l1);
                        st_h2(dh+o,h0,h1); st_h2(dl+o,l0,l1);
                    }
                } else if(EPI==2){
                    int b=z/12, hh=z-b*12;
                    long long o=(long long)(b*1024+r)*768 + hh*64 + c;
                    st_h2(p.o1+o, __float2half_rn(v0), __float2half_rn(v1));
                } else if(EPI==3){
                    long long o=(long long)r*p.ldo + c;
                    float2 rr=*(const float2*)(p.res+o);
                    float2 ov; ov.x=v0+p.bias[c]+rr.x; ov.y=v1+p.bias[c+1]+rr.y;
                    *(float2*)(p.outf+o)=ov;
                } else if(EPI==4){
                    v0+=p.bias[c]; v1+=p.bias[c+1];
                    v0=0.5f*v0*(1.0f+erff(v0*0.70710678118654752f));
                    v1=0.5f*v1*(1.0f+erff(v1*0.70710678118654752f));
                    long long o=(long long)r*p.ldoh + c;
                    st_h2(p.o1+o, __float2half_rn(v0), __float2half_rn(v1));
                }
            }
        }
    }
}

// ---------------- LayerNorm ----------------
__global__ void ln_kernel(const float* __restrict__ in, const float* __restrict__ g,
                          const float* __restrict__ b, float* __restrict__ outf,
                          hf* __restrict__ oh){
    int row=blockIdx.x, tid=threadIdx.x;
    const float* x = in + (long long)row*768;
    float xv[3], s=0.f, ss=0.f;
    #pragma unroll
    for(int i=0;i<3;i++){ float v=x[tid+i*256]; xv[i]=v; s+=v; ss+=v*v; }
    __shared__ float red[64];
    #pragma unroll
    for(int o=16;o>0;o>>=1){ s+=__shfl_down_sync(~0u,s,o); ss+=__shfl_down_sync(~0u,ss,o); }
    int warp=tid>>5, lane=tid&31;
    if(lane==0){ red[warp]=s; red[32+warp]=ss; }
    __syncthreads();
    if(warp==0){
        s=(lane<8)?red[lane]:0.f; ss=(lane<8)?red[32+lane]:0.f;
        #pragma unroll
        for(int o=4;o>0;o>>=1){ s+=__shfl_down_sync(~0u,s,o); ss+=__shfl_down_sync(~0u,ss,o); }
        if(lane==0){ red[0]=s; red[1]=ss; }
    }
    __syncthreads();
    float mu=red[0]*(1.f/768), var=red[1]*(1.f/768)-mu*mu, rstd=rsqrtf(var+1e-5f);
    #pragma unroll
    for(int i=0;i<3;i++){
        int c=tid+i*256;
        float v=(xv[i]-mu)*rstd*g[c]+b[c];
        long long o=(long long)row*768+c;
        if(outf) outf[o]=v;
        if(oh) oh[o]=__float2half_rn(v);
    }
}

// ---------------- fused mix->softmax->mix, single global pass ----------------
#define MSP 1024
__global__ void __launch_bounds__(256) mixsoftmax(
    const float* __restrict__ S, hf* __restrict__ P,
    const float* __restrict__ tb, const float* __restrict__ ta){
    extern __shared__ float sh[];                    // 12*MSP e-values
    __shared__ float tbs[144], tas[144], wsum[8][12], rin[12];
    int tid=threadIdx.x, warp=tid>>5, lane=tid&31;
    if(tid<144){ tbs[tid]=tb[tid]; tas[tid]=ta[tid]; }
    __syncthreads();
    int bn=blockIdx.x, b=bn>>10, n=bn&1023;
    long long base=((long long)b*NHEAD*1024+n)*1024;
    float sm[12];
    #pragma unroll
    for(int g=0;g<12;g++) sm[g]=0.f;
    #pragma unroll 1
    for(int j=0;j<4;j++){
        int m=tid+j*256;
        float s[12];
        #pragma unroll
        for(int h=0;h<12;h++) s[h]=S[base+h*HSs+m];
        #pragma unroll
        for(int g=0;g<12;g++){
            float v=0.f;
            #pragma unroll
            for(int h=0;h<12;h++) v=fmaf(tbs[g*12+h],s[h],v);
            float e=__expf(v);
            sh[g*MSP+m]=e; sm[g]+=e;
        }
    }
    #pragma unroll
    for(int o=16;o>0;o>>=1){
        #pragma unroll
        for(int g=0;g<12;g++) sm[g]+=__shfl_xor_sync(~0u,sm[g],o);
    }
    if(lane==0){
        #pragma unroll
        for(int g=0;g<12;g++) wsum[warp][g]=sm[g];
    }
    __syncthreads();
    if(tid<12){
        float t=0.f;
        #pragma unroll
        for(int w=0;w<8;w++) t+=wsum[w][tid];
        rin[tid]=1.f/t;
    }
    __syncthreads();
    float RS[12];
    #pragma unroll
    for(int g=0;g<12;g++) RS[g]=rin[g];
    #pragma unroll 1
    for(int j=0;j<4;j++){
        int m=tid+j*256;
        float e[12];
        #pragma unroll
        for(int h=0;h<12;h++) e[h]=sh[h*MSP+m]*RS[h];
        #pragma unroll
        for(int g=0;g<12;g++){
            float v=0.f;
            #pragma unroll
            for(int h=0;h<12;h++) v=fmaf(tas[g*12+h],e[h],v);
            P[base+g*HSs+m]=__float2half_rn(v);
        }
    }
}

// ---------------- depthwise conv + fused weight convert ----------------
__global__ void dwconv_kernel(const float* __restrict__ in, const float* __restrict__ w,
                              const float* __restrict__ bias, float* __restrict__ out){
    int idx=blockIdx.x*256+threadIdx.x;
    int c=idx%768, bn=idx/768, n=bn&1023, b=bn>>10;
    const float* xp = in + (long long)b*1024*768 + c;
    float acc=bias[c];
    #pragma unroll
    for(int k=0;k<7;k++){
        int m=n+k-3;
        if(m>=0 && m<1024) acc+=w[c*7+k]*xp[(long long)m*768];
    }
    out[idx]=acc;
}
__global__ void wconv(const float* __restrict__ w1,const float* __restrict__ w2,
                      const float* __restrict__ w3,const float* __restrict__ w4,
                      hf* o1h,hf* o1l,hf* o2h,hf* o2l,hf* o3h,hf* o3l,hf* o4h,hf* o4l){
    int i=blockIdx.x*256+threadIdx.x;
    const float* s; hf *oh,*ol; int j=i;
    if(j<1769472){ s=w1; oh=o1h; ol=o1l; }
    else if((j-=1769472)<589824){ s=w2; oh=o2h; ol=o2l; }
    else if((j-=589824)<2359296){ s=w3; oh=o3h; ol=o3l; }
    else { j-=2359296; s=w4; oh=o4h; ol=o4l; }
    hf h,l; hilo(s[j],h,l); oh[j]=h; ol[j]=l;
}

// ---------------- launch ----------------
extern "C" void kernel_launch(void* const* d_in, const int* in_sizes, int n_in,
                              void* d_out, int out_size){
    const float *x=(const float*)d_in[0], *w_qkv=(const float*)d_in[1], *b_qkv=(const float*)d_in[2];
    const float *w_proj=(const float*)d_in[3], *b_proj=(const float*)d_in[4];
    const float *w_fc1=(const float*)d_in[5], *b_fc1=(const float*)d_in[6];
    const float *w_fc2=(const float*)d_in[7], *b_fc2=(const float*)d_in[8];
    const float *t_before=(const float*)d_in[9], *t_after=(const float*)d_in[10];
    const float *g1=(const float*)d_in[11], *be1=(const float*)d_in[12];
    const float *g2=(const float*)d_in[13], *be2=(const float*)d_in[14];
    const float *dw_w=(const float*)d_in[15], *dw_b=(const float*)d_in[16];
    const float *gm=(const float*)d_in[17], *bm=(const float*)d_in[18];
    float* out=(float*)d_out;

    float *pS,*px2,*ph2,*pcv;
    hf *pP,*pq,*pkh,*pkl,*pvh,*pvl,*ph1,*pa,*pm,*pf;
    hf *w1h,*w1l,*w2h,*w2l,*w3h,*w3l,*w4h,*w4l;
    cudaGetSymbolAddress((void**)&pS,g_S);   cudaGetSymbolAddress((void**)&px2,g_x2);
    cudaGetSymbolAddress((void**)&ph2,g_h2); cudaGetSymbolAddress((void**)&pcv,g_cv);
    cudaGetSymbolAddress((void**)&pP,g_P);   cudaGetSymbolAddress((void**)&pq,g_q);
    cudaGetSymbolAddress((void**)&pkh,g_kh); cudaGetSymbolAddress((void**)&pkl,g_kl);
    cudaGetSymbolAddress((void**)&pvh,g_vh); cudaGetSymbolAddress((void**)&pvl,g_vl);
    cudaGetSymbolAddress((void**)&ph1,g_h1); cudaGetSymbolAddress((void**)&pa,g_a);
    cudaGetSymbolAddress((void**)&pm,g_m);   cudaGetSymbolAddress((void**)&pf,g_f);
    cudaGetSymbolAddress((void**)&w1h,g_w1h);cudaGetSymbolAddress((void**)&w1l,g_w1l);
    cudaGetSymbolAddress((void**)&w2h,g_w2h);cudaGetSymbolAddress((void**)&w2l,g_w2l);
    cudaGetSymbolAddress((void**)&w3h,g_w3h);cudaGetSymbolAddress((void**)&w3l,g_w3l);
    cudaGetSymbolAddress((void**)&w4h,g_w4h);cudaGetSymbolAddress((void**)&w4l,g_w4l);

    const int S128 = 2*(128*40*2 + 2*128*40*2);    // 61440
    const int S64  = 2*(128*40*2 + 2*64*40*2);     // 40960
    const int SMIX = 12*MSP*4;                      // 49152
    cudaFuncSetAttribute(mma_gemm<128,0,true>, cudaFuncAttributeMaxDynamicSharedMemorySize, S128);
    cudaFuncSetAttribute(mma_gemm<128,1,true>, cudaFuncAttributeMaxDynamicSharedMemorySize, S128);
    cudaFuncSetAttribute(mma_gemm<64,2,false>, cudaFuncAttributeMaxDynamicSharedMemorySize, S64);
    cudaFuncSetAttribute(mma_gemm<128,3,true>, cudaFuncAttributeMaxDynamicSharedMemorySize, S128);
    cudaFuncSetAttribute(mma_gemm<128,4,true>, cudaFuncAttributeMaxDynamicSharedMemorySize, S128);
    cudaFuncSetAttribute(mixsoftmax, cudaFuncAttributeMaxDynamicSharedMemorySize, SMIX);

    wconv<<<27648,256>>>(w_qkv,w_proj,w_fc1,w_fc2,w1h,w1l,w2h,w2l,w3h,w3l,w4h,w4l);
    ln_kernel<<<ROWS,256>>>(x,g1,be1,nullptr,ph1);

    GP p{};
    // QKV: h1 @ w_qkv^T + b -> q (fp16), k/v (hi/lo)
    p.Ah=ph1; p.Bh=w1h; p.Bl=w1l; p.K=768; p.lda=768; p.ldb=768;
    p.bias=b_qkv; p.o1=pq; p.kh=pkh; p.kl=pkl; p.vh=pvh; p.vl=pvl;
    mma_gemm<128,1,true><<<dim3(18,32,1),256,S128>>>(p);

    // QK^T per (b,h): S = Q K^T * 0.125
    p=GP{}; p.Ah=pq; p.Bh=pkh; p.Bl=pkl;
    p.K=64; p.lda=64; p.ldb=64; p.sAz=65536; p.sBz=65536; p.sOz=HSs;
    p.outf=pS; p.ldo=1024; p.alpha=0.125f;
    mma_gemm<128,0,true><<<dim3(8,8,48),256,S128>>>(p);

    mixsoftmax<<<ROWS,256,SMIX>>>(pS,pP,t_before,t_after);

    // AV per (b,h): P[1024,1024] @ V[1024,64] -> attn[B,N,C]
    p=GP{}; p.Ah=pP; p.Bh=pvh; p.Bl=pvl;
    p.K=1024; p.lda=1024; p.ldb=64; p.sAz=HSs; p.sBz=65536;
    p.o1=pa;
    mma_gemm<64,2,false><<<dim3(1,8,48),256,S64>>>(p);

    // proj + bias + residual(x) -> x2
    p=GP{}; p.Ah=pa; p.Bh=w2h; p.Bl=w2l;
    p.K=768; p.lda=768; p.ldb=768; p.bias=b_proj; p.res=x; p.outf=px2; p.ldo=768;
    mma_gemm<128,3,true><<<dim3(6,32,1),256,S128>>>(p);

    ln_kernel<<<ROWS,256>>>(px2,g2,be2,ph2,nullptr);
    dwconv_kernel<<<ROWS*768/256,256>>>(ph2,dw_w,dw_b,pcv);
    ln_kernel<<<ROWS,256>>>(pcv,gm,bm,nullptr,pm);

    // fc1 + bias + gelu -> f (fp16)
    p=GP{}; p.Ah=pm; p.Bh=w3h; p.Bl=w3l;
    p.K=768; p.lda=768; p.ldb=768; p.bias=b_fc1; p.o1=pf; p.ldoh=3072;
    mma_gemm<128,4,true><<<dim3(24,32,1),256,S128>>>(p);

    // fc2 + bias + residual(x2) -> out
    p=GP{}; p.Ah=pf; p.Bh=w4h; p.Bl=w4l;
    p.K=3072; p.lda=3072; p.ldb=3072; p.bias=b_fc2; p.res=px2; p.outf=out; p.ldo=768;
    mma_gemm<128,3,true><<<dim3(6,32,1),256,S128>>>(p);
}

// round 7
// speedup vs baseline: 3.5805x; 1.0760x over previous
#include <cuda_runtime.h>
#include <cuda_fp16.h>
#include <math.h>
#include <stdint.h>
typedef __half hf;

#define NHEAD 12
#define ROWS  4096
#define HSs   1048576LL

// ---------------- scratch ----------------
__device__ __align__(16) hf    g_S  [50331648];                   // fp16 scores
__device__ __align__(16) hf    g_P  [50331648];
__device__ __align__(16) hf    g_q  [3145728];                    // [B,H,N,64]
__device__ __align__(16) hf    g_k  [3145728];
__device__ __align__(16) hf    g_v  [3145728];
__device__ __align__(16) hf    g_h1 [3145728];
__device__ __align__(16) hf    g_a  [3145728];
__device__ __align__(16) hf    g_m  [3145728];
__device__ __align__(16) hf    g_f  [12582912];
__device__ __align__(16) float g_x2 [3145728], g_h2[3145728], g_cv[3145728];
__device__ __align__(16) hf    g_w1h[1769472], g_w1l[1769472];
__device__ __align__(16) hf    g_w2h[589824],  g_w2l[589824];
__device__ __align__(16) hf    g_w3h[2359296], g_w3l[2359296];
__device__ __align__(16) hf    g_w4h[2359296], g_w4l[2359296];

__device__ __forceinline__ uint32_t smem_u32(const void* p){
    uint32_t a; asm("{ .reg .u64 t; cvta.to.shared.u64 t, %1; cvt.u32.u64 %0, t; }":"=r"(a):"l"(p)); return a;
}
#define LDM4(r0,r1,r2,r3,ad) asm volatile("ldmatrix.sync.aligned.m8n8.x4.shared.b16 {%0,%1,%2,%3},[%4];" \
    : "=r"(r0),"=r"(r1),"=r"(r2),"=r"(r3):"r"(ad))
#define MMA(d,a,b) asm volatile( \
    "mma.sync.aligned.m16n8k16.row.col.f32.f16.f16.f32 {%0,%1,%2,%3},{%4,%5,%6,%7},{%8,%9},{%0,%1,%2,%3};" \
    : "+f"((d)[0]),"+f"((d)[1]),"+f"((d)[2]),"+f"((d)[3]) \
    : "r"((a)[0]),"r"((a)[1]),"r"((a)[2]),"r"((a)[3]),"r"((b)[0]),"r"((b)[1]))
#define CPA(dst,src) asm volatile("cp.async.cg.shared.global [%0],[%1],16;"::"r"(dst),"l"(src))
#define CPCOMMIT()   asm volatile("cp.async.commit_group;":::"memory")
#define CPWAIT0()    asm volatile("cp.async.wait_group 0;":::"memory")
#define CPWAIT1()    asm volatile("cp.async.wait_group 1;":::"memory")

__device__ __forceinline__ void hilo(float v, hf&h, hf&l){
    h=__float2half_rn(v); l=__float2half_rn(v-__half2float(h));
}
__device__ __forceinline__ void st_h2(hf* p, float a, float b){
    __half2 t; t.x=__float2half_rn(a); t.y=__float2half_rn(b); *(__half2*)p = t;
}

struct GP {
    const hf *Ah,*Bh,*Bl;
    int K, lda, ldb;
    long long sAz, sBz, sOz;
    float alpha;
    const float *bias, *res;
    float *outf; int ldo;
    hf *o1; int ldoh;          // fp16 out (EPI 0/2/4) or Q (EPI 1)
    hf *kd,*vd;                // EPI 1 targets
};

// C[M,N] = A[M,K] @ op(B): A single fp16; B fp16 (hi/lo iff HASBL).
// BT: B is [N,K] k-contig; else [K,N]. 3-stage cp.async pipeline.
// EPI: 0=alpha->fp16 batched, 1=QKV scatter, 2=AV->[B,N,C] fp16, 3=bias+res f32, 4=bias+gelu fp16
template<int BN,int EPI,bool BT,bool HASBL>
__global__ void __launch_bounds__(256) mma_gemm(GP p){
    constexpr int WARPS_N = BN/32;
    constexpr int WM = 128/(8/WARPS_N);
    constexpr int MT = WM/16;
    constexpr int PAD = 40;
    constexpr int ABYT = 128*PAD*2;
    constexpr int BBYT = BN*PAD*2;
    constexpr int STG  = ABYT + (HASBL?2:1)*BBYT;

    extern __shared__ char dsm[];
    const uint32_t sb = smem_u32(dsm);
    const int tid=threadIdx.x, wid=tid>>5, lane=tid&31;
    const int z=blockIdx.z, m0=blockIdx.y*128, n0=blockIdx.x*BN;
    const int wm_=wid/WARPS_N, wn_=wid%WARPS_N;

    const hf* Ah=p.Ah+(long long)z*p.sAz;
    const hf* Bh=p.Bh+(long long)z*p.sBz;
    const hf* Bl=HASBL?(p.Bl+(long long)z*p.sBz):nullptr;

    float acc[MT][4][4];
    #pragma unroll
    for(int i=0;i<MT;i++)
        #pragma unroll
        for(int j=0;j<4;j++)
            #pragma unroll
            for(int e=0;e<4;e++) acc[i][j][e]=0.f;

    auto load_stage=[&](int t,int s){
        const long long k0=(long long)t<<5;
        const uint32_t b0 = sb + s*STG;
        #pragma unroll
        for(int i=tid;i<512;i+=256){
            int row=i>>2, seg=i&3;
            uint32_t d = b0 + (row*PAD+seg*8)*2;
            long long g=(long long)(m0+row)*p.lda + k0 + seg*8;
            CPA(d, Ah+g);
        }
        if(BT){
            #pragma unroll
            for(int i=tid;i<BN*4;i+=256){
                int row=i>>2, seg=i&3;
                uint32_t d=b0+ABYT+(row*PAD+seg*8)*2;
                long long g=(long long)(n0+row)*p.ldb + k0 + seg*8;
                CPA(d, Bh+g);
                if(HASBL) CPA(d+BBYT, Bl+g);
            }
        } else {
            hf* sh_=(hf*)(dsm + s*STG + ABYT);
            #pragma unroll
            for(int i=tid;i<BN*4;i+=256){
                int tt=i>>3, ds=i&7;
                long long g=(long long)(k0+tt)*p.ldb + n0 + ds*8;
                uint4 vh=*(const uint4*)(Bh+g);
                const hf* eh=(const hf*)&vh;
                #pragma unroll
                for(int e=0;e<8;e++) sh_[(ds*8+e)*PAD+tt]=eh[e];
            }
        }
        CPCOMMIT();
    };

    auto compute=[&](int s){
        const uint32_t bA=sb+s*STG, bB=bA+ABYT, bBl=bB+BBYT;
        #pragma unroll
        for(int kk=0;kk<32;kk+=16){
            uint32_t bh[4][2], bl[4][2];
            #pragma unroll
            for(int nt=0;nt<2;nt++){
                int row = wn_*32 + nt*16 + (lane&7) + ((lane>>4)&1)*8;
                int ko  = kk + ((lane>>3)&1)*8;
                uint32_t off=(uint32_t)(row*PAD+ko)*2;
                LDM4(bh[2*nt][0],bh[2*nt][1],bh[2*nt+1][0],bh[2*nt+1][1], bB+off);
                if(HASBL){ LDM4(bl[2*nt][0],bl[2*nt][1],bl[2*nt+1][0],bl[2*nt+1][1], bBl+off); }
            }
            #pragma unroll
            for(int mi=0;mi<MT;mi++){
                int row = wm_*WM + mi*16 + (lane&7) + ((lane>>3)&1)*8;
                int ko  = kk + ((lane>>4)&1)*8;
                uint32_t off=(uint32_t)(row*PAD+ko)*2;
                uint32_t ah[4];
                LDM4(ah[0],ah[1],ah[2],ah[3], bA+off);
                #pragma unroll
                for(int ni=0;ni<4;ni++){
                    MMA(acc[mi][ni],ah,bh[ni]);
                    if(HASBL) MMA(acc[mi][ni],ah,bl[ni]);
                }
            }
        }
    };

    const int T = p.K>>5;
    load_stage(0,0);
    if(T>1) load_stage(1,1);
    for(int t=0;t<T;t++){
        if(t+1<T){ CPWAIT1(); } else { CPWAIT0(); }
        __syncthreads();
        if(t+2<T) load_stage(t+2,(t+2)%3);
        compute(t%3);
    }

    // -------- epilogue --------
    const int rb = m0 + wm_*WM, cbse = n0 + wn_*32;
    #pragma unroll
    for(int mi=0;mi<MT;mi++){
        #pragma unroll
        for(int ni=0;ni<4;ni++){
            #pragma unroll
            for(int half=0;half<2;half++){
                int r = rb + mi*16 + (lane>>2) + half*8;
                int c = cbse + ni*8 + (lane&3)*2;
                float v0=acc[mi][ni][half*2], v1=acc[mi][ni][half*2+1];
                if(EPI==0){
                    st_h2(p.o1 + (long long)z*p.sOz + (long long)r*p.ldo + c,
                          v0*p.alpha, v1*p.alpha);
                } else if(EPI==1){
                    v0+=p.bias[c]; v1+=p.bias[c+1];
                    int b=r>>10, n=r&1023;
                    hf* dst = (c<768)?p.o1 : ((c<1536)?p.kd:p.vd);
                    int cc  = (c<768)?c   : ((c<1536)?c-768:c-1536);
                    int hh=cc>>6, d=cc&63;
                    long long o=((long long)(b*12+hh)*1024+n)*64+d;
                    st_h2(dst+o, v0, v1);
                } else if(EPI==2){
                    int b=z/12, hh=z-b*12;
                    long long o=(long long)(b*1024+r)*768 + hh*64 + c;
                    st_h2(p.o1+o, v0, v1);
                } else if(EPI==3){
                    long long o=(long long)r*p.ldo + c;
                    float2 rr=*(const float2*)(p.res+o);
                    float2 ov; ov.x=v0+p.bias[c]+rr.x; ov.y=v1+p.bias[c+1]+rr.y;
                    *(float2*)(p.outf+o)=ov;
                } else if(EPI==4){
                    v0+=p.bias[c]; v1+=p.bias[c+1];
                    v0=0.5f*v0*(1.0f+erff(v0*0.70710678118654752f));
                    v1=0.5f*v1*(1.0f+erff(v1*0.70710678118654752f));
                    st_h2(p.o1+(long long)r*p.ldoh+c, v0, v1);
                }
            }
        }
    }
}

// ---------------- LayerNorm ----------------
__global__ void ln_kernel(const float* __restrict__ in, const float* __restrict__ g,
                          const float* __restrict__ b, float* __restrict__ outf,
                          hf* __restrict__ oh){
    int row=blockIdx.x, tid=threadIdx.x;
    const float* x = in + (long long)row*768;
    float xv[3], s=0.f, ss=0.f;
    #pragma unroll
    for(int i=0;i<3;i++){ float v=x[tid+i*256]; xv[i]=v; s+=v; ss+=v*v; }
    __shared__ float red[64];
    #pragma unroll
    for(int o=16;o>0;o>>=1){ s+=__shfl_down_sync(~0u,s,o); ss+=__shfl_down_sync(~0u,ss,o); }
    int warp=tid>>5, lane=tid&31;
    if(lane==0){ red[warp]=s; red[32+warp]=ss; }
    __syncthreads();
    if(warp==0){
        s=(lane<8)?red[lane]:0.f; ss=(lane<8)?red[32+lane]:0.f;
        #pragma unroll
        for(int o=4;o>0;o>>=1){ s+=__shfl_down_sync(~0u,s,o); ss+=__shfl_down_sync(~0u,ss,o); }
        if(lane==0){ red[0]=s; red[1]=ss; }
    }
    __syncthreads();
    float mu=red[0]*(1.f/768), var=red[1]*(1.f/768)-mu*mu, rstd=rsqrtf(var+1e-5f);
    #pragma unroll
    for(int i=0;i<3;i++){
        int c=tid+i*256;
        float v=(xv[i]-mu)*rstd*g[c]+b[c];
        long long o=(long long)row*768+c;
        if(outf) outf[o]=v;
        if(oh) oh[o]=__float2half_rn(v);
    }
}

// ---------------- fused mix->softmax->mix, single global pass ----------------
#define MSP 1024
__global__ void __launch_bounds__(256) mixsoftmax(
    const hf* __restrict__ S, hf* __restrict__ P,
    const float* __restrict__ tb, const float* __restrict__ ta){
    extern __shared__ float sh[];                    // 12*MSP e-values
    __shared__ float tbs[144], tas[144], wsum[8][12], rin[12];
    int tid=threadIdx.x, warp=tid>>5, lane=tid&31;
    if(tid<144){ tbs[tid]=tb[tid]; tas[tid]=ta[tid]; }
    __syncthreads();
    int bn=blockIdx.x, b=bn>>10, n=bn&1023;
    long long base=((long long)b*NHEAD*1024+n)*1024;
    float sm[12];
    #pragma unroll
    for(int g=0;g<12;g++) sm[g]=0.f;
    #pragma unroll 1
    for(int j=0;j<4;j++){
        int m=tid+j*256;
        float s[12];
        #pragma unroll
        for(int h=0;h<12;h++) s[h]=__half2float(S[base+h*HSs+m]);
        #pragma unroll
        for(int g=0;g<12;g++){
            float v=0.f;
            #pragma unroll
            for(int h=0;h<12;h++) v=fmaf(tbs[g*12+h],s[h],v);
            float e=__expf(v);
            sh[g*MSP+m]=e; sm[g]+=e;
        }
    }
    #pragma unroll
    for(int o=16;o>0;o>>=1){
        #pragma unroll
        for(int g=0;g<12;g++) sm[g]+=__shfl_xor_sync(~0u,sm[g],o);
    }
    if(lane==0){
        #pragma unroll
        for(int g=0;g<12;g++) wsum[warp][g]=sm[g];
    }
    __syncthreads();
    if(tid<12){
        float t=0.f;
        #pragma unroll
        for(int w=0;w<8;w++) t+=wsum[w][tid];
        rin[tid]=1.f/t;
    }
    __syncthreads();
    float RS[12];
    #pragma unroll
    for(int g=0;g<12;g++) RS[g]=rin[g];
    #pragma unroll 1
    for(int j=0;j<4;j++){
        int m=tid+j*256;
        float e[12];
        #pragma unroll
        for(int h=0;h<12;h++) e[h]=sh[h*MSP+m]*RS[h];
        #pragma unroll
        for(int g=0;g<12;g++){
            float v=0.f;
            #pragma unroll
            for(int h=0;h<12;h++) v=fmaf(tas[g*12+h],e[h],v);
            P[base+g*HSs+m]=__float2half_rn(v);
        }
    }
}

// ---------------- depthwise conv + fused weight convert ----------------
__global__ void dwconv_kernel(const float* __restrict__ in, const float* __restrict__ w,
                              const float* __restrict__ bias, float* __restrict__ out){
    int idx=blockIdx.x*256+threadIdx.x;
    int c=idx%768, bn=idx/768, n=bn&1023, b=bn>>10;
    const float* xp = in + (long long)b*1024*768 + c;
    float acc=bias[c];
    #pragma unroll
    for(int k=0;k<7;k++){
        int m=n+k-3;
        if(m>=0 && m<1024) acc+=w[c*7+k]*xp[(long long)m*768];
    }
    out[idx]=acc;
}
__global__ void wconv(const float* __restrict__ w1,const float* __restrict__ w2,
                      const float* __restrict__ w3,const float* __restrict__ w4,
                      hf* o1h,hf* o1l,hf* o2h,hf* o2l,hf* o3h,hf* o3l,hf* o4h,hf* o4l){
    int i=blockIdx.x*256+threadIdx.x;
    const float* s; hf *oh,*ol; int j=i;
    if(j<1769472){ s=w1; oh=o1h; ol=o1l; }
    else if((j-=1769472)<589824){ s=w2; oh=o2h; ol=o2l; }
    else if((j-=589824)<2359296){ s=w3; oh=o3h; ol=o3l; }
    else { j-=2359296; s=w4; oh=o4h; ol=o4l; }
    hf h,l; hilo(s[j],h,l); oh[j]=h; ol[j]=l;
}

// ---------------- launch ----------------
extern "C" void kernel_launch(void* const* d_in, const int* in_sizes, int n_in,
                              void* d_out, int out_size){
    const float *x=(const float*)d_in[0], *w_qkv=(const float*)d_in[1], *b_qkv=(const float*)d_in[2];
    const float *w_proj=(const float*)d_in[3], *b_proj=(const float*)d_in[4];
    const float *w_fc1=(const float*)d_in[5], *b_fc1=(const float*)d_in[6];
    const float *w_fc2=(const float*)d_in[7], *b_fc2=(const float*)d_in[8];
    const float *t_before=(const float*)d_in[9], *t_after=(const float*)d_in[10];
    const float *g1=(const float*)d_in[11], *be1=(const float*)d_in[12];
    const float *g2=(const float*)d_in[13], *be2=(const float*)d_in[14];
    const float *dw_w=(const float*)d_in[15], *dw_b=(const float*)d_in[16];
    const float *gm=(const float*)d_in[17], *bm=(const float*)d_in[18];
    float* out=(float*)d_out;

    float *px2,*ph2,*pcv;
    hf *pS,*pP,*pq,*pk,*pv,*ph1,*pa,*pm,*pf;
    hf *w1h,*w1l,*w2h,*w2l,*w3h,*w3l,*w4h,*w4l;
    cudaGetSymbolAddress((void**)&pS,g_S);   cudaGetSymbolAddress((void**)&px2,g_x2);
    cudaGetSymbolAddress((void**)&ph2,g_h2); cudaGetSymbolAddress((void**)&pcv,g_cv);
    cudaGetSymbolAddress((void**)&pP,g_P);   cudaGetSymbolAddress((void**)&pq,g_q);
    cudaGetSymbolAddress((void**)&pk,g_k);   cudaGetSymbolAddress((void**)&pv,g_v);
    cudaGetSymbolAddress((void**)&ph1,g_h1); cudaGetSymbolAddress((void**)&pa,g_a);
    cudaGetSymbolAddress((void**)&pm,g_m);   cudaGetSymbolAddress((void**)&pf,g_f);
    cudaGetSymbolAddress((void**)&w1h,g_w1h);cudaGetSymbolAddress((void**)&w1l,g_w1l);
    cudaGetSymbolAddress((void**)&w2h,g_w2h);cudaGetSymbolAddress((void**)&w2l,g_w2l);
    cudaGetSymbolAddress((void**)&w3h,g_w3h);cudaGetSymbolAddress((void**)&w3l,g_w3l);
    cudaGetSymbolAddress((void**)&w4h,g_w4h);cudaGetSymbolAddress((void**)&w4l,g_w4l);

    const int PADB = 40*2;
    const int S128HL = 3*(128*PADB + 2*128*PADB);   // 92160
    const int S128S  = 3*(128*PADB + 128*PADB);     // 61440
    const int S64S   = 3*(128*PADB + 64*PADB);      // 46080
    const int SMIX = 12*MSP*4;
    cudaFuncSetAttribute(mma_gemm<128,0,true,false>, cudaFuncAttributeMaxDynamicSharedMemorySize, S128S);
    cudaFuncSetAttribute(mma_gemm<128,1,true,true>,  cudaFuncAttributeMaxDynamicSharedMemorySize, S128HL);
    cudaFuncSetAttribute(mma_gemm<64,2,false,false>, cudaFuncAttributeMaxDynamicSharedMemorySize, S64S);
    cudaFuncSetAttribute(mma_gemm<128,3,true,true>,  cudaFuncAttributeMaxDynamicSharedMemorySize, S128HL);
    cudaFuncSetAttribute(mma_gemm<128,4,true,true>,  cudaFuncAttributeMaxDynamicSharedMemorySize, S128HL);
    cudaFuncSetAttribute(mixsoftmax, cudaFuncAttributeMaxDynamicSharedMemorySize, SMIX);

    wconv<<<27648,256>>>(w_qkv,w_proj,w_fc1,w_fc2,w1h,w1l,w2h,w2l,w3h,w3l,w4h,w4l);
    ln_kernel<<<ROWS,256>>>(x,g1,be1,nullptr,ph1);

    GP p{};
    // QKV: h1 @ w_qkv^T + b -> q, k, v (all fp16)
    p.Ah=ph1; p.Bh=w1h; p.Bl=w1l; p.K=768; p.lda=768; p.ldb=768;
    p.bias=b_qkv; p.o1=pq; p.kd=pk; p.vd=pv;
    mma_gemm<128,1,true,true><<<dim3(18,32,1),256,S128HL>>>(p);

    // QK^T per (b,h): S = Q K^T * 0.125 (fp16 out)
    p=GP{}; p.Ah=pq; p.Bh=pk;
    p.K=64; p.lda=64; p.ldb=64; p.sAz=65536; p.sBz=65536; p.sOz=HSs;
    p.o1=pS; p.ldo=1024; p.alpha=0.125f;
    mma_gemm<128,0,true,false><<<dim3(8,8,48),256,S128S>>>(p);

    mixsoftmax<<<ROWS,256,SMIX>>>(pS,pP,t_before,t_after);

    // AV per (b,h): P[1024,1024] @ V[1024,64] -> attn[B,N,C]
    p=GP{}; p.Ah=pP; p.Bh=pv;
    p.K=1024; p.lda=1024; p.ldb=64; p.sAz=HSs; p.sBz=65536;
    p.o1=pa;
    mma_gemm<64,2,false,false><<<dim3(1,8,48),256,S64S>>>(p);

    // proj + bias + residual(x) -> x2
    p=GP{}; p.Ah=pa; p.Bh=w2h; p.Bl=w2l;
    p.K=768; p.lda=768; p.ldb=768; p.bias=b_proj; p.res=x; p.outf=px2; p.ldo=768;
    mma_gemm<128,3,true,true><<<dim3(6,32,1),256,S128HL>>>(p);

    ln_kernel<<<ROWS,256>>>(px2,g2,be2,ph2,nullptr);
    dwconv_kernel<<<ROWS*768/256,256>>>(ph2,dw_w,dw_b,pcv);
    ln_kernel<<<ROWS,256>>>(pcv,gm,bm,nullptr,pm);

    // fc1 + bias + gelu -> f (fp16)
    p=GP{}; p.Ah=pm; p.Bh=w3h; p.Bl=w3l;
    p.K=768; p.lda=768; p.ldb=768; p.bias=b_fc1; p.o1=pf; p.ldoh=3072;
    mma_gemm<128,4,true,true><<<dim3(24,32,1),256,S128HL>>>(p);

    // fc2 + bias + residual(x2) -> out
    p=GP{}; p.Ah=pf; p.Bh=w4h; p.Bl=w4l;
    p.K=3072; p.lda=3072; p.ldb=3072; p.bias=b_fc2; p.res=px2; p.outf=out; p.ldo=768;
    mma_gemm<128,3,true,true><<<dim3(6,32,1),256,S128HL>>>(p);
}

// round 8
// speedup vs baseline: 4.6865x; 1.3089x over previous
#include <cuda_runtime.h>
#include <cuda_fp16.h>
#include <math.h>
#include <stdint.h>
typedef __half hf;

#define NHEAD 12
#define ROWS  4096
#define HSs   1048576LL

// ---------------- scratch ----------------
__device__ __align__(16) hf    g_S  [50331648];
__device__ __align__(16) hf    g_P  [50331648];
__device__ __align__(16) hf    g_q  [3145728];                    // [B,H,N,64]
__device__ __align__(16) hf    g_k  [3145728];
__device__ __align__(16) hf    g_v  [3145728];
__device__ __align__(16) hf    g_h1 [3145728];
__device__ __align__(16) hf    g_a  [3145728];
__device__ __align__(16) hf    g_m  [3145728];
__device__ __align__(16) hf    g_f  [12582912];
__device__ __align__(16) float g_x2 [3145728], g_h2[3145728], g_cv[3145728];
__device__ __align__(16) hf    g_w1 [1769472];
__device__ __align__(16) hf    g_w2 [589824];
__device__ __align__(16) hf    g_w3 [2359296];
__device__ __align__(16) hf    g_w4 [2359296];

__device__ __forceinline__ uint32_t smem_u32(const void* p){
    uint32_t a; asm("{ .reg .u64 t; cvta.to.shared.u64 t, %1; cvt.u32.u64 %0, t; }":"=r"(a):"l"(p)); return a;
}
#define LDM4(r0,r1,r2,r3,ad) asm volatile("ldmatrix.sync.aligned.m8n8.x4.shared.b16 {%0,%1,%2,%3},[%4];" \
    : "=r"(r0),"=r"(r1),"=r"(r2),"=r"(r3):"r"(ad))
#define MMA(d,a,b) asm volatile( \
    "mma.sync.aligned.m16n8k16.row.col.f32.f16.f16.f32 {%0,%1,%2,%3},{%4,%5,%6,%7},{%8,%9},{%0,%1,%2,%3};" \
    : "+f"((d)[0]),"+f"((d)[1]),"+f"((d)[2]),"+f"((d)[3]) \
    : "r"((a)[0]),"r"((a)[1]),"r"((a)[2]),"r"((a)[3]),"r"((b)[0]),"r"((b)[1]))
#define CPA(dst,src) asm volatile("cp.async.cg.shared.global [%0],[%1],16;"::"r"(dst),"l"(src))
#define CPCOMMIT()   asm volatile("cp.async.commit_group;":::"memory")
#define CPWAIT0()    asm volatile("cp.async.wait_group 0;":::"memory")
#define CPWAIT1()    asm volatile("cp.async.wait_group 1;":::"memory")

__device__ __forceinline__ void st_h2(hf* p, float a, float b){
    __half2 t; t.x=__float2half_rn(a); t.y=__float2half_rn(b); *(__half2*)p = t;
}

struct GP {
    const hf *Ah,*Bh;
    int K, lda, ldb;
    long long sAz, sBz, sOz;
    float alpha;
    const float *bias, *res;
    float *outf; int ldo;
    hf *o1; int ldoh;          // fp16 out (EPI 0/2/4) or Q (EPI 1)
    hf *kd,*vd;                // EPI 1 targets
};

// C[M,N] = A[M,K] @ op(B), both single fp16 (1 MMA product).
// BT: B is [N,K] k-contig; else [K,N]. 3-stage cp.async pipeline.
// EPI: 0=alpha->fp16 batched, 1=QKV scatter, 2=AV->[B,N,C] fp16, 3=bias+res f32, 4=bias+gelu fp16
template<int BN,int EPI,bool BT>
__global__ void __launch_bounds__(256) mma_gemm(GP p){
    constexpr int WARPS_N = BN/32;
    constexpr int WM = 128/(8/WARPS_N);
    constexpr int MT = WM/16;
    constexpr int PAD = 40;
    constexpr int ABYT = 128*PAD*2;
    constexpr int BBYT = BN*PAD*2;
    constexpr int STG  = ABYT + BBYT;

    extern __shared__ char dsm[];
    const uint32_t sb = smem_u32(dsm);
    const int tid=threadIdx.x, wid=tid>>5, lane=tid&31;
    const int z=blockIdx.z, m0=blockIdx.y*128, n0=blockIdx.x*BN;
    const int wm_=wid/WARPS_N, wn_=wid%WARPS_N;

    const hf* Ah=p.Ah+(long long)z*p.sAz;
    const hf* Bh=p.Bh+(long long)z*p.sBz;

    float acc[MT][4][4];
    #pragma unroll
    for(int i=0;i<MT;i++)
        #pragma unroll
        for(int j=0;j<4;j++)
            #pragma unroll
            for(int e=0;e<4;e++) acc[i][j][e]=0.f;

    auto load_stage=[&](int t,int s){
        const long long k0=(long long)t<<5;
        const uint32_t b0 = sb + s*STG;
        #pragma unroll
        for(int i=tid;i<512;i+=256){
            int row=i>>2, seg=i&3;
            uint32_t d = b0 + (row*PAD+seg*8)*2;
            long long g=(long long)(m0+row)*p.lda + k0 + seg*8;
            CPA(d, Ah+g);
        }
        if(BT){
            #pragma unroll
            for(int i=tid;i<BN*4;i+=256){
                int row=i>>2, seg=i&3;
                uint32_t d=b0+ABYT+(row*PAD+seg*8)*2;
                long long g=(long long)(n0+row)*p.ldb + k0 + seg*8;
                CPA(d, Bh+g);
            }
        } else {
            hf* sh_=(hf*)(dsm + s*STG + ABYT);
            #pragma unroll
            for(int i=tid;i<BN*4;i+=256){
                int tt=i>>3, ds=i&7;
                long long g=(long long)(k0+tt)*p.ldb + n0 + ds*8;
                uint4 vh=*(const uint4*)(Bh+g);
                const hf* eh=(const hf*)&vh;
                #pragma unroll
                for(int e=0;e<8;e++) sh_[(ds*8+e)*PAD+tt]=eh[e];
            }
        }
        CPCOMMIT();
    };

    auto compute=[&](int s){
        const uint32_t bA=sb+s*STG, bB=bA+ABYT;
        #pragma unroll
        for(int kk=0;kk<32;kk+=16){
            uint32_t bh[4][2];
            #pragma unroll
            for(int nt=0;nt<2;nt++){
                int row = wn_*32 + nt*16 + (lane&7) + ((lane>>4)&1)*8;
                int ko  = kk + ((lane>>3)&1)*8;
                uint32_t off=(uint32_t)(row*PAD+ko)*2;
                LDM4(bh[2*nt][0],bh[2*nt][1],bh[2*nt+1][0],bh[2*nt+1][1], bB+off);
            }
            #pragma unroll
            for(int mi=0;mi<MT;mi++){
                int row = wm_*WM + mi*16 + (lane&7) + ((lane>>3)&1)*8;
                int ko  = kk + ((lane>>4)&1)*8;
                uint32_t off=(uint32_t)(row*PAD+ko)*2;
                uint32_t ah[4];
                LDM4(ah[0],ah[1],ah[2],ah[3], bA+off);
                #pragma unroll
                for(int ni=0;ni<4;ni++) MMA(acc[mi][ni],ah,bh[ni]);
            }
        }
    };

    const int T = p.K>>5;
    load_stage(0,0);
    if(T>1) load_stage(1,1);
    for(int t=0;t<T;t++){
        if(t+1<T){ CPWAIT1(); } else { CPWAIT0(); }
        __syncthreads();
        if(t+2<T) load_stage(t+2,(t+2)%3);
        compute(t%3);
    }

    // -------- epilogue --------
    const int rb = m0 + wm_*WM, cbse = n0 + wn_*32;
    #pragma unroll
    for(int mi=0;mi<MT;mi++){
        #pragma unroll
        for(int ni=0;ni<4;ni++){
            #pragma unroll
            for(int half=0;half<2;half++){
                int r = rb + mi*16 + (lane>>2) + half*8;
                int c = cbse + ni*8 + (lane&3)*2;
                float v0=acc[mi][ni][half*2], v1=acc[mi][ni][half*2+1];
                if(EPI==0){
                    st_h2(p.o1 + (long long)z*p.sOz + (long long)r*p.ldo + c,
                          v0*p.alpha, v1*p.alpha);
                } else if(EPI==1){
                    v0+=p.bias[c]; v1+=p.bias[c+1];
                    int b=r>>10, n=r&1023;
                    hf* dst = (c<768)?p.o1 : ((c<1536)?p.kd:p.vd);
                    int cc  = (c<768)?c   : ((c<1536)?c-768:c-1536);
                    int hh=cc>>6, d=cc&63;
                    long long o=((long long)(b*12+hh)*1024+n)*64+d;
                    st_h2(dst+o, v0, v1);
                } else if(EPI==2){
                    int b=z/12, hh=z-b*12;
                    long long o=(long long)(b*1024+r)*768 + hh*64 + c;
                    st_h2(p.o1+o, v0, v1);
                } else if(EPI==3){
                    long long o=(long long)r*p.ldo + c;
                    float2 rr=*(const float2*)(p.res+o);
                    float2 ov; ov.x=v0+p.bias[c]+rr.x; ov.y=v1+p.bias[c+1]+rr.y;
                    *(float2*)(p.outf+o)=ov;
                } else if(EPI==4){
                    v0+=p.bias[c]; v1+=p.bias[c+1];
                    v0=0.5f*v0*(1.0f+erff(v0*0.70710678118654752f));
                    v1=0.5f*v1*(1.0f+erff(v1*0.70710678118654752f));
                    st_h2(p.o1+(long long)r*p.ldoh+c, v0, v1);
                }
            }
        }
    }
}

// ---------------- LayerNorm ----------------
__global__ void ln_kernel(const float* __restrict__ in, const float* __restrict__ g,
                          const float* __restrict__ b, float* __restrict__ outf,
                          hf* __restrict__ oh){
    int row=blockIdx.x, tid=threadIdx.x;
    const float* x = in + (long long)row*768;
    float xv[3], s=0.f, ss=0.f;
    #pragma unroll
    for(int i=0;i<3;i++){ float v=x[tid+i*256]; xv[i]=v; s+=v; ss+=v*v; }
    __shared__ float red[64];
    #pragma unroll
    for(int o=16;o>0;o>>=1){ s+=__shfl_down_sync(~0u,s,o); ss+=__shfl_down_sync(~0u,ss,o); }
    int warp=tid>>5, lane=tid&31;
    if(lane==0){ red[warp]=s; red[32+warp]=ss; }
    __syncthreads();
    if(warp==0){
        s=(lane<8)?red[lane]:0.f; ss=(lane<8)?red[32+lane]:0.f;
        #pragma unroll
        for(int o=4;o>0;o>>=1){ s+=__shfl_down_sync(~0u,s,o); ss+=__shfl_down_sync(~0u,ss,o); }
        if(lane==0){ red[0]=s; red[1]=ss; }
    }
    __syncthreads();
    float mu=red[0]*(1.f/768), var=red[1]*(1.f/768)-mu*mu, rstd=rsqrtf(var+1e-5f);
    #pragma unroll
    for(int i=0;i<3;i++){
        int c=tid+i*256;
        float v=(xv[i]-mu)*rstd*g[c]+b[c];
        long long o=(long long)row*768+c;
        if(outf) outf[o]=v;
        if(oh) oh[o]=__float2half_rn(v);
    }
}

// ---------------- fused mix->softmax->mix, single global pass ----------------
#define MSP 1024
__global__ void __launch_bounds__(256) mixsoftmax(
    const hf* __restrict__ S, hf* __restrict__ P,
    const float* __restrict__ tb, const float* __restrict__ ta){
    extern __shared__ float sh[];
    __shared__ float tbs[144], tas[144], wsum[8][12], rin[12];
    int tid=threadIdx.x, warp=tid>>5, lane=tid&31;
    if(tid<144){ tbs[tid]=tb[tid]; tas[tid]=ta[tid]; }
    __syncthreads();
    int bn=blockIdx.x, b=bn>>10, n=bn&1023;
    long long base=((long long)b*NHEAD*1024+n)*1024;
    float sm[12];
    #pragma unroll
    for(int g=0;g<12;g++) sm[g]=0.f;
    #pragma unroll 1
    for(int j=0;j<4;j++){
        int m=tid+j*256;
        float s[12];
        #pragma unroll
        for(int h=0;h<12;h++) s[h]=__half2float(S[base+h*HSs+m]);
        #pragma unroll
        for(int g=0;g<12;g++){
            float v=0.f;
            #pragma unroll
            for(int h=0;h<12;h++) v=fmaf(tbs[g*12+h],s[h],v);
            float e=__expf(v);
            sh[g*MSP+m]=e; sm[g]+=e;
        }
    }
    #pragma unroll
    for(int o=16;o>0;o>>=1){
        #pragma unroll
        for(int g=0;g<12;g++) sm[g]+=__shfl_xor_sync(~0u,sm[g],o);
    }
    if(lane==0){
        #pragma unroll
        for(int g=0;g<12;g++) wsum[warp][g]=sm[g];
    }
    __syncthreads();
    if(tid<12){
        float t=0.f;
        #pragma unroll
        for(int w=0;w<8;w++) t+=wsum[w][tid];
        rin[tid]=1.f/t;
    }
    __syncthreads();
    float RS[12];
    #pragma unroll
    for(int g=0;g<12;g++) RS[g]=rin[g];
    #pragma unroll 1
    for(int j=0;j<4;j++){
        int m=tid+j*256;
        float e[12];
        #pragma unroll
        for(int h=0;h<12;h++) e[h]=sh[h*MSP+m]*RS[h];
        #pragma unroll
        for(int g=0;g<12;g++){
            float v=0.f;
            #pragma unroll
            for(int h=0;h<12;h++) v=fmaf(tas[g*12+h],e[h],v);
            P[base+g*HSs+m]=__float2half_rn(v);
        }
    }
}

// ---------------- depthwise conv + weight convert ----------------
__global__ void dwconv_kernel(const float* __restrict__ in, const float* __restrict__ w,
                              const float* __restrict__ bias, float* __restrict__ out){
    int idx=blockIdx.x*256+threadIdx.x;
    int c=idx%768, bn=idx/768, n=bn&1023, b=bn>>10;
    const float* xp = in + (long long)b*1024*768 + c;
    float acc=bias[c];
    #pragma unroll
    for(int k=0;k<7;k++){
        int m=n+k-3;
        if(m>=0 && m<1024) acc+=w[c*7+k]*xp[(long long)m*768];
    }
    out[idx]=acc;
}
__global__ void wconv(const float* __restrict__ w1,const float* __restrict__ w2,
                      const float* __restrict__ w3,const float* __restrict__ w4,
                      hf* o1,hf* o2,hf* o3,hf* o4){
    int i=blockIdx.x*256+threadIdx.x;
    const float* s; hf *oh; int j=i;
    if(j<1769472){ s=w1; oh=o1; }
    else if((j-=1769472)<589824){ s=w2; oh=o2; }
    else if((j-=589824)<2359296){ s=w3; oh=o3; }
    else { j-=2359296; s=w4; oh=o4; }
    oh[j]=__float2half_rn(s[j]);
}

// ---------------- launch ----------------
extern "C" void kernel_launch(void* const* d_in, const int* in_sizes, int n_in,
                              void* d_out, int out_size){
    const float *x=(const float*)d_in[0], *w_qkv=(const float*)d_in[1], *b_qkv=(const float*)d_in[2];
    const float *w_proj=(const float*)d_in[3], *b_proj=(const float*)d_in[4];
    const float *w_fc1=(const float*)d_in[5], *b_fc1=(const float*)d_in[6];
    const float *w_fc2=(const float*)d_in[7], *b_fc2=(const float*)d_in[8];
    const float *t_before=(const float*)d_in[9], *t_after=(const float*)d_in[10];
    const float *g1=(const float*)d_in[11], *be1=(const float*)d_in[12];
    const float *g2=(const float*)d_in[13], *be2=(const float*)d_in[14];
    const float *dw_w=(const float*)d_in[15], *dw_b=(const float*)d_in[16];
    const float *gm=(const float*)d_in[17], *bm=(const float*)d_in[18];
    float* out=(float*)d_out;

    float *px2,*ph2,*pcv;
    hf *pS,*pP,*pq,*pk,*pv,*ph1,*pa,*pm,*pf,*w1,*w2,*w3,*w4;
    cudaGetSymbolAddress((void**)&pS,g_S);   cudaGetSymbolAddress((void**)&px2,g_x2);
    cudaGetSymbolAddress((void**)&ph2,g_h2); cudaGetSymbolAddress((void**)&pcv,g_cv);
    cudaGetSymbolAddress((void**)&pP,g_P);   cudaGetSymbolAddress((void**)&pq,g_q);
    cudaGetSymbolAddress((void**)&pk,g_k);   cudaGetSymbolAddress((void**)&pv,g_v);
    cudaGetSymbolAddress((void**)&ph1,g_h1); cudaGetSymbolAddress((void**)&pa,g_a);
    cudaGetSymbolAddress((void**)&pm,g_m);   cudaGetSymbolAddress((void**)&pf,g_f);
    cudaGetSymbolAddress((void**)&w1,g_w1);  cudaGetSymbolAddress((void**)&w2,g_w2);
    cudaGetSymbolAddress((void**)&w3,g_w3);  cudaGetSymbolAddress((void**)&w4,g_w4);

    const int PADB = 40*2;
    const int S128 = 3*(128*PADB + 128*PADB);   // 61440
    const int S64  = 3*(128*PADB + 64*PADB);    // 46080
    const int SMIX = 12*MSP*4;
    cudaFuncSetAttribute(mma_gemm<128,0,true>,  cudaFuncAttributeMaxDynamicSharedMemorySize, S128);
    cudaFuncSetAttribute(mma_gemm<128,1,true>,  cudaFuncAttributeMaxDynamicSharedMemorySize, S128);
    cudaFuncSetAttribute(mma_gemm<64,2,false>,  cudaFuncAttributeMaxDynamicSharedMemorySize, S64);
    cudaFuncSetAttribute(mma_gemm<128,3,true>,  cudaFuncAttributeMaxDynamicSharedMemorySize, S128);
    cudaFuncSetAttribute(mma_gemm<128,4,true>,  cudaFuncAttributeMaxDynamicSharedMemorySize, S128);
    cudaFuncSetAttribute(mixsoftmax, cudaFuncAttributeMaxDynamicSharedMemorySize, SMIX);

    wconv<<<27648,256>>>(w_qkv,w_proj,w_fc1,w_fc2,w1,w2,w3,w4);
    ln_kernel<<<ROWS,256>>>(x,g1,be1,nullptr,ph1);

    GP p{};
    // QKV: h1 @ w_qkv^T + b -> q, k, v
    p.Ah=ph1; p.Bh=w1; p.K=768; p.lda=768; p.ldb=768;
    p.bias=b_qkv; p.o1=pq; p.kd=pk; p.vd=pv;
    mma_gemm<128,1,true><<<dim3(18,32,1),256,S128>>>(p);

    // QK^T per (b,h): S = Q K^T * 0.125
    p=GP{}; p.Ah=pq; p.Bh=pk;
    p.K=64; p.lda=64; p.ldb=64; p.sAz=65536; p.sBz=65536; p.sOz=HSs;
    p.o1=pS; p.ldo=1024; p.alpha=0.125f;
    mma_gemm<128,0,true><<<dim3(8,8,48),256,S128>>>(p);

    mixsoftmax<<<ROWS,256,SMIX>>>(pS,pP,t_before,t_after);

    // AV per (b,h): P @ V -> attn[B,N,C]
    p=GP{}; p.Ah=pP; p.Bh=pv;
    p.K=1024; p.lda=1024; p.ldb=64; p.sAz=HSs; p.sBz=65536;
    p.o1=pa;
    mma_gemm<64,2,false><<<dim3(1,8,48),256,S64>>>(p);

    // proj + bias + residual(x) -> x2
    p=GP{}; p.Ah=pa; p.Bh=w2;
    p.K=768; p.lda=768; p.ldb=768; p.bias=b_proj; p.res=x; p.outf=px2; p.ldo=768;
    mma_gemm<128,3,true><<<dim3(6,32,1),256,S128>>>(p);

    ln_kernel<<<ROWS,256>>>(px2,g2,be2,ph2,nullptr);
    dwconv_kernel<<<ROWS*768/256,256>>>(ph2,dw_w,dw_b,pcv);
    ln_kernel<<<ROWS,256>>>(pcv,gm,bm,nullptr,pm);

    // fc1 + bias + gelu -> f
    p=GP{}; p.Ah=pm; p.Bh=w3;
    p.K=768; p.lda=768; p.ldb=768; p.bias=b_fc1; p.o1=pf; p.ldoh=3072;
    mma_gemm<128,4,true><<<dim3(24,32,1),256,S128>>>(p);

    // fc2 + bias + residual(x2) -> out
    p=GP{}; p.Ah=pf; p.Bh=w4;
    p.K=3072; p.lda=3072; p.ldb=3072; p.bias=b_fc2; p.res=px2; p.outf=out; p.ldo=768;
    mma_gemm<128,3,true><<<dim3(6,32,1),256,S128>>>(p);
}

// round 9
// speedup vs baseline: 5.0741x; 1.0827x over previous
#include <cuda_runtime.h>
#include <cuda_fp16.h>
#include <math.h>
#include <stdint.h>
typedef __half hf;

#define NHEAD 12
#define ROWS  4096
#define HSs   1048576LL

// ---------------- scratch ----------------
__device__ __align__(16) hf    g_S  [50331648];
__device__ __align__(16) hf    g_P  [50331648];
__device__ __align__(16) hf    g_q  [3145728];                    // [B,H,N,64]
__device__ __align__(16) hf    g_k  [3145728];
__device__ __align__(16) hf    g_v  [3145728];
__device__ __align__(16) hf    g_h1 [3145728];
__device__ __align__(16) hf    g_a  [3145728];
__device__ __align__(16) hf    g_m  [3145728];
__device__ __align__(16) hf    g_f  [12582912];
__device__ __align__(16) float g_x2 [3145728], g_h2[3145728];
__device__ __align__(16) hf    g_w1 [1769472];
__device__ __align__(16) hf    g_w2 [589824];
__device__ __align__(16) hf    g_w3 [2359296];
__device__ __align__(16) hf    g_w4 [2359296];

__device__ __forceinline__ uint32_t smem_u32(const void* p){
    uint32_t a; asm("{ .reg .u64 t; cvta.to.shared.u64 t, %1; cvt.u32.u64 %0, t; }":"=r"(a):"l"(p)); return a;
}
#define LDM4(r0,r1,r2,r3,ad) asm volatile("ldmatrix.sync.aligned.m8n8.x4.shared.b16 {%0,%1,%2,%3},[%4];" \
    : "=r"(r0),"=r"(r1),"=r"(r2),"=r"(r3):"r"(ad))
#define MMA(d,a,b) asm volatile( \
    "mma.sync.aligned.m16n8k16.row.col.f32.f16.f16.f32 {%0,%1,%2,%3},{%4,%5,%6,%7},{%8,%9},{%0,%1,%2,%3};" \
    : "+f"((d)[0]),"+f"((d)[1]),"+f"((d)[2]),"+f"((d)[3]) \
    : "r"((a)[0]),"r"((a)[1]),"r"((a)[2]),"r"((a)[3]),"r"((b)[0]),"r"((b)[1]))
#define CPA(dst,src) asm volatile("cp.async.cg.shared.global [%0],[%1],16;"::"r"(dst),"l"(src))
#define CPCOMMIT()   asm volatile("cp.async.commit_group;":::"memory")
#define CPWAIT0()    asm volatile("cp.async.wait_group 0;":::"memory")
#define CPWAIT1()    asm volatile("cp.async.wait_group 1;":::"memory")

__device__ __forceinline__ void st_h2(hf* p, float a, float b){
    __half2 t; t.x=__float2half_rn(a); t.y=__float2half_rn(b); *(__half2*)p = t;
}

struct GP {
    const hf *Ah,*Bh;
    int K, lda, ldb;
    long long sAz, sBz, sOz;
    float alpha;
    const float *bias, *res;
    float *outf; int ldo;
    hf *o1; int ldoh;
    hf *kd,*vd;
};

// C[M,N] = A[M,K] @ op(B), single fp16 product. BT: B is [N,K] k-contig; else [K,N].
// 3-stage cp.async pipeline. Tiles BM x BN, 8 warps as (8/(BN/32)) x (BN/32).
// EPI: 0=alpha->fp16 batched, 1=QKV scatter, 2=AV->[B,N,C] fp16, 3=bias+res f32, 4=bias+gelu fp16
template<int BM,int BN,int EPI,bool BT>
__global__ void __launch_bounds__(256) mma_gemm(GP p){
    constexpr int WARPS_N = BN/32;
    constexpr int WARPS_M = 8/WARPS_N;
    constexpr int WM = BM/WARPS_M;
    constexpr int MT = WM/16;
    constexpr int PAD = 40;
    constexpr int ABYT = BM*PAD*2;
    constexpr int BBYT = BN*PAD*2;
    constexpr int STG  = ABYT + BBYT;

    extern __shared__ char dsm[];
    const uint32_t sb = smem_u32(dsm);
    const int tid=threadIdx.x, wid=tid>>5, lane=tid&31;
    const int z=blockIdx.z, m0=blockIdx.y*BM, n0=blockIdx.x*BN;
    const int wm_=wid/WARPS_N, wn_=wid%WARPS_N;

    const hf* Ah=p.Ah+(long long)z*p.sAz;
    const hf* Bh=p.Bh+(long long)z*p.sBz;

    float acc[MT][4][4];
    #pragma unroll
    for(int i=0;i<MT;i++)
        #pragma unroll
        for(int j=0;j<4;j++)
            #pragma unroll
            for(int e=0;e<4;e++) acc[i][j][e]=0.f;

    auto load_stage=[&](int t,int s){
        const long long k0=(long long)t<<5;
        const uint32_t b0 = sb + s*STG;
        #pragma unroll
        for(int i=tid;i<BM*4;i+=256){
            int row=i>>2, seg=i&3;
            uint32_t d = b0 + (row*PAD+seg*8)*2;
            long long g=(long long)(m0+row)*p.lda + k0 + seg*8;
            CPA(d, Ah+g);
        }
        if(BT){
            #pragma unroll
            for(int i=tid;i<BN*4;i+=256){
                int row=i>>2, seg=i&3;
                uint32_t d=b0+ABYT+(row*PAD+seg*8)*2;
                long long g=(long long)(n0+row)*p.ldb + k0 + seg*8;
                CPA(d, Bh+g);
            }
        } else {
            hf* sh_=(hf*)(dsm + s*STG + ABYT);
            #pragma unroll
            for(int i=tid;i<BN*4;i+=256){
                int tt=i>>3, ds=i&7;
                long long g=(long long)(k0+tt)*p.ldb + n0 + ds*8;
                uint4 vh=*(const uint4*)(Bh+g);
                const hf* eh=(const hf*)&vh;
                #pragma unroll
                for(int e=0;e<8;e++) sh_[(ds*8+e)*PAD+tt]=eh[e];
            }
        }
        CPCOMMIT();
    };

    auto compute=[&](int s){
        const uint32_t bA=sb+s*STG, bB=bA+ABYT;
        #pragma unroll
        for(int kk=0;kk<32;kk+=16){
            uint32_t bh[4][2];
            #pragma unroll
            for(int nt=0;nt<2;nt++){
                int row = wn_*32 + nt*16 + (lane&7) + ((lane>>4)&1)*8;
                int ko  = kk + ((lane>>3)&1)*8;
                uint32_t off=(uint32_t)(row*PAD+ko)*2;
                LDM4(bh[2*nt][0],bh[2*nt][1],bh[2*nt+1][0],bh[2*nt+1][1], bB+off);
            }
            #pragma unroll
            for(int mi=0;mi<MT;mi++){
                int row = wm_*WM + mi*16 + (lane&7) + ((lane>>3)&1)*8;
                int ko  = kk + ((lane>>4)&1)*8;
                uint32_t off=(uint32_t)(row*PAD+ko)*2;
                uint32_t ah[4];
                LDM4(ah[0],ah[1],ah[2],ah[3], bA+off);
                #pragma unroll
                for(int ni=0;ni<4;ni++) MMA(acc[mi][ni],ah,bh[ni]);
            }
        }
    };

    const int T = p.K>>5;
    load_stage(0,0);
    if(T>1) load_stage(1,1);
    for(int t=0;t<T;t++){
        if(t+1<T){ CPWAIT1(); } else { CPWAIT0(); }
        __syncthreads();
        if(t+2<T) load_stage(t+2,(t+2)%3);
        compute(t%3);
    }

    // -------- epilogue --------
    const int rb = m0 + wm_*WM, cbse = n0 + wn_*32;
    #pragma unroll
    for(int mi=0;mi<MT;mi++){
        #pragma unroll
        for(int ni=0;ni<4;ni++){
            #pragma unroll
            for(int half=0;half<2;half++){
                int r = rb + mi*16 + (lane>>2) + half*8;
                int c = cbse + ni*8 + (lane&3)*2;
                float v0=acc[mi][ni][half*2], v1=acc[mi][ni][half*2+1];
                if(EPI==0){
                    st_h2(p.o1 + (long long)z*p.sOz + (long long)r*p.ldo + c,
                          v0*p.alpha, v1*p.alpha);
                } else if(EPI==1){
                    v0+=p.bias[c]; v1+=p.bias[c+1];
                    int b=r>>10, n=r&1023;
                    hf* dst = (c<768)?p.o1 : ((c<1536)?p.kd:p.vd);
                    int cc  = (c<768)?c   : ((c<1536)?c-768:c-1536);
                    int hh=cc>>6, d=cc&63;
                    long long o=((long long)(b*12+hh)*1024+n)*64+d;
                    st_h2(dst+o, v0, v1);
                } else if(EPI==2){
                    int b=z/12, hh=z-b*12;
                    long long o=(long long)(b*1024+r)*768 + hh*64 + c;
                    st_h2(p.o1+o, v0, v1);
                } else if(EPI==3){
                    long long o=(long long)r*p.ldo + c;
                    float2 rr=*(const float2*)(p.res+o);
                    float2 ov; ov.x=v0+p.bias[c]+rr.x; ov.y=v1+p.bias[c+1]+rr.y;
                    *(float2*)(p.outf+o)=ov;
                } else if(EPI==4){
                    v0+=p.bias[c]; v1+=p.bias[c+1];
                    v0=0.5f*v0*(1.0f+erff(v0*0.70710678118654752f));
                    v1=0.5f*v1*(1.0f+erff(v1*0.70710678118654752f));
                    st_h2(p.o1+(long long)r*p.ldoh+c, v0, v1);
                }
            }
        }
    }
}

// ---------------- LayerNorm ----------------
__global__ void ln_kernel(const float* __restrict__ in, const float* __restrict__ g,
                          const float* __restrict__ b, float* __restrict__ outf,
                          hf* __restrict__ oh){
    int row=blockIdx.x, tid=threadIdx.x;
    const float* x = in + (long long)row*768;
    float xv[3], s=0.f, ss=0.f;
    #pragma unroll
    for(int i=0;i<3;i++){ float v=x[tid+i*256]; xv[i]=v; s+=v; ss+=v*v; }
    __shared__ float red[64];
    #pragma unroll
    for(int o=16;o>0;o>>=1){ s+=__shfl_down_sync(~0u,s,o); ss+=__shfl_down_sync(~0u,ss,o); }
    int warp=tid>>5, lane=tid&31;
    if(lane==0){ red[warp]=s; red[32+warp]=ss; }
    __syncthreads();
    if(warp==0){
        s=(lane<8)?red[lane]:0.f; ss=(lane<8)?red[32+lane]:0.f;
        #pragma unroll
        for(int o=4;o>0;o>>=1){ s+=__shfl_down_sync(~0u,s,o); ss+=__shfl_down_sync(~0u,ss,o); }
        if(lane==0){ red[0]=s; red[1]=ss; }
    }
    __syncthreads();
    float mu=red[0]*(1.f/768), var=red[1]*(1.f/768)-mu*mu, rstd=rsqrtf(var+1e-5f);
    #pragma unroll
    for(int i=0;i<3;i++){
        int c=tid+i*256;
        float v=(xv[i]-mu)*rstd*g[c]+b[c];
        long long o=(long long)row*768+c;
        if(outf) outf[o]=v;
        if(oh) oh[o]=__float2half_rn(v);
    }
}

// ---------------- fused mix->softmax->mix, fp16 slab + half2 I/O ----------------
__global__ void __launch_bounds__(256) mixsoftmax(
    const hf* __restrict__ S, hf* __restrict__ P,
    const float* __restrict__ tb, const float* __restrict__ ta){
    extern __shared__ __half2 sh2[];                 // 12*512 half2
    __shared__ float tbs[144], tas[144], wsum[8][12], rin[12];
    int tid=threadIdx.x, warp=tid>>5, lane=tid&31;
    if(tid<144){ tbs[tid]=tb[tid]; tas[tid]=ta[tid]; }
    __syncthreads();
    int bn=blockIdx.x, b=bn>>10, n=bn&1023;
    long long base=((long long)b*NHEAD*1024+n)*1024;
    float sm[12];
    #pragma unroll
    for(int g=0;g<12;g++) sm[g]=0.f;
    #pragma unroll 1
    for(int jj=0;jj<2;jj++){
        int mp=tid+jj*256;                           // half2 index (2 m's)
        float2 s[12];
        #pragma unroll
        for(int h=0;h<12;h++) s[h]=__half22float2(*(const __half2*)(S+base+h*HSs+2*mp));
        #pragma unroll
        for(int g=0;g<12;g++){
            float v0=0.f, v1=0.f;
            #pragma unroll
            for(int h=0;h<12;h++){ v0=fmaf(tbs[g*12+h],s[h].x,v0); v1=fmaf(tbs[g*12+h],s[h].y,v1); }
            float e0=__expf(v0), e1=__expf(v1);
            sh2[g*512+mp]=__floats2half2_rn(e0,e1);
            sm[g]+=e0+e1;
        }
    }
    #pragma unroll
    for(int o=16;o>0;o>>=1){
        #pragma unroll
        for(int g=0;g<12;g++) sm[g]+=__shfl_xor_sync(~0u,sm[g],o);
    }
    if(lane==0){
        #pragma unroll
        for(int g=0;g<12;g++) wsum[warp][g]=sm[g];
    }
    __syncthreads();
    if(tid<12){
        float t=0.f;
        #pragma unroll
        for(int w=0;w<8;w++) t+=wsum[w][tid];
        rin[tid]=1.f/t;
    }
    __syncthreads();
    float RS[12];
    #pragma unroll
    for(int g=0;g<12;g++) RS[g]=rin[g];
    #pragma unroll 1
    for(int jj=0;jj<2;jj++){
        int mp=tid+jj*256;
        float2 e[12];
        #pragma unroll
        for(int h=0;h<12;h++){
            e[h]=__half22float2(sh2[h*512+mp]);
            e[h].x*=RS[h]; e[h].y*=RS[h];
        }
        #pragma unroll
        for(int g=0;g<12;g++){
            float v0=0.f, v1=0.f;
            #pragma unroll
            for(int h=0;h<12;h++){ v0=fmaf(tas[g*12+h],e[h].x,v0); v1=fmaf(tas[g*12+h],e[h].y,v1); }
            *(__half2*)(P+base+g*HSs+2*mp)=__floats2half2_rn(v0,v1);
        }
    }
}

// ---------------- fused depthwise conv + LN(gm,bm) ----------------
__global__ void dwln_kernel(const float* __restrict__ in, const float* __restrict__ w,
                            const float* __restrict__ bias, const float* __restrict__ gm,
                            const float* __restrict__ bm, hf* __restrict__ om){
    int row=blockIdx.x, tid=threadIdx.x;
    int b=row>>10, n=row&1023;
    const float* xp = in + (long long)b*1024*768;
    float acc[3], s=0.f, ss=0.f;
    #pragma unroll
    for(int i=0;i<3;i++){
        int c=tid+i*256;
        float a=bias[c];
        #pragma unroll
        for(int k=0;k<7;k++){
            int m=n+k-3;
            if(m>=0 && m<1024) a+=w[c*7+k]*xp[(long long)m*768+c];
        }
        acc[i]=a; s+=a; ss+=a*a;
    }
    __shared__ float red[64];
    #pragma unroll
    for(int o=16;o>0;o>>=1){ s+=__shfl_down_sync(~0u,s,o); ss+=__shfl_down_sync(~0u,ss,o); }
    int warp=tid>>5, lane=tid&31;
    if(lane==0){ red[warp]=s; red[32+warp]=ss; }
    __syncthreads();
    if(warp==0){
        s=(lane<8)?red[lane]:0.f; ss=(lane<8)?red[32+lane]:0.f;
        #pragma unroll
        for(int o=4;o>0;o>>=1){ s+=__shfl_down_sync(~0u,s,o); ss+=__shfl_down_sync(~0u,ss,o); }
        if(lane==0){ red[0]=s; red[1]=ss; }
    }
    __syncthreads();
    float mu=red[0]*(1.f/768), var=red[1]*(1.f/768)-mu*mu, rstd=rsqrtf(var+1e-5f);
    #pragma unroll
    for(int i=0;i<3;i++){
        int c=tid+i*256;
        om[(long long)row*768+c]=__float2half_rn((acc[i]-mu)*rstd*gm[c]+bm[c]);
    }
}

__global__ void wconv(const float* __restrict__ w1,const float* __restrict__ w2,
                      const float* __restrict__ w3,const float* __restrict__ w4,
                      hf* o1,hf* o2,hf* o3,hf* o4){
    int i=blockIdx.x*256+threadIdx.x;
    const float* s; hf *oh; int j=i;
    if(j<1769472){ s=w1; oh=o1; }
    else if((j-=1769472)<589824){ s=w2; oh=o2; }
    else if((j-=589824)<2359296){ s=w3; oh=o3; }
    else { j-=2359296; s=w4; oh=o4; }
    oh[j]=__float2half_rn(s[j]);
}

// ---------------- launch ----------------
extern "C" void kernel_launch(void* const* d_in, const int* in_sizes, int n_in,
                              void* d_out, int out_size){
    const float *x=(const float*)d_in[0], *w_qkv=(const float*)d_in[1], *b_qkv=(const float*)d_in[2];
    const float *w_proj=(const float*)d_in[3], *b_proj=(const float*)d_in[4];
    const float *w_fc1=(const float*)d_in[5], *b_fc1=(const float*)d_in[6];
    const float *w_fc2=(const float*)d_in[7], *b_fc2=(const float*)d_in[8];
    const float *t_before=(const float*)d_in[9], *t_after=(const float*)d_in[10];
    const float *g1=(const float*)d_in[11], *be1=(const float*)d_in[12];
    const float *g2=(const float*)d_in[13], *be2=(const float*)d_in[14];
    const float *dw_w=(const float*)d_in[15], *dw_b=(const float*)d_in[16];
    const float *gm=(const float*)d_in[17], *bm=(const float*)d_in[18];
    float* out=(float*)d_out;

    float *px2,*ph2;
    hf *pS,*pP,*pq,*pk,*pv,*ph1,*pa,*pm,*pf,*w1,*w2,*w3,*w4;
    cudaGetSymbolAddress((void**)&pS,g_S);   cudaGetSymbolAddress((void**)&px2,g_x2);
    cudaGetSymbolAddress((void**)&ph2,g_h2);
    cudaGetSymbolAddress((void**)&pP,g_P);   cudaGetSymbolAddress((void**)&pq,g_q);
    cudaGetSymbolAddress((void**)&pk,g_k);   cudaGetSymbolAddress((void**)&pv,g_v);
    cudaGetSymbolAddress((void**)&ph1,g_h1); cudaGetSymbolAddress((void**)&pa,g_a);
    cudaGetSymbolAddress((void**)&pm,g_m);   cudaGetSymbolAddress((void**)&pf,g_f);
    cudaGetSymbolAddress((void**)&w1,g_w1);  cudaGetSymbolAddress((void**)&w2,g_w2);
    cudaGetSymbolAddress((void**)&w3,g_w3);  cudaGetSymbolAddress((void**)&w4,g_w4);

    const int PADB = 40*2;
    const int S128128 = 3*(128+128)*PADB;   // 61440
    const int S12864  = 3*(128+64)*PADB;    // 46080
    const int S6464   = 3*(64+64)*PADB;     // 30720
    const int S64128  = 3*(64+128)*PADB;    // 46080
    const int SMIX = 12*512*4;              // 24576
    cudaFuncSetAttribute(mma_gemm<128,128,1,true>, cudaFuncAttributeMaxDynamicSharedMemorySize, S128128);
    cudaFuncSetAttribute(mma_gemm<128,64,0,true>,  cudaFuncAttributeMaxDynamicSharedMemorySize, S12864);
    cudaFuncSetAttribute(mma_gemm<64,64,2,false>,  cudaFuncAttributeMaxDynamicSharedMemorySize, S6464);
    cudaFuncSetAttribute(mma_gemm<64,128,3,true>,  cudaFuncAttributeMaxDynamicSharedMemorySize, S64128);
    cudaFuncSetAttribute(mma_gemm<128,128,4,true>, cudaFuncAttributeMaxDynamicSharedMemorySize, S128128);
    cudaFuncSetAttribute(mixsoftmax, cudaFuncAttributeMaxDynamicSharedMemorySize, SMIX);

    wconv<<<27648,256>>>(w_qkv,w_proj,w_fc1,w_fc2,w1,w2,w3,w4);
    ln_kernel<<<ROWS,256>>>(x,g1,be1,nullptr,ph1);

    GP p{};
    // QKV: h1 @ w_qkv^T + b -> q, k, v
    p.Ah=ph1; p.Bh=w1; p.K=768; p.lda=768; p.ldb=768;
    p.bias=b_qkv; p.o1=pq; p.kd=pk; p.vd=pv;
    mma_gemm<128,128,1,true><<<dim3(18,32,1),256,S128128>>>(p);

    // QK^T per (b,h): S = Q K^T * 0.125
    p=GP{}; p.Ah=pq; p.Bh=pk;
    p.K=64; p.lda=64; p.ldb=64; p.sAz=65536; p.sBz=65536; p.sOz=HSs;
    p.o1=pS; p.ldo=1024; p.alpha=0.125f;
    mma_gemm<128,64,0,true><<<dim3(16,8,48),256,S12864>>>(p);

    mixsoftmax<<<ROWS,256,SMIX>>>(pS,pP,t_before,t_after);

    // AV per (b,h): P @ V -> attn[B,N,C]
    p=GP{}; p.Ah=pP; p.Bh=pv;
    p.K=1024; p.lda=1024; p.ldb=64; p.sAz=HSs; p.sBz=65536;
    p.o1=pa;
    mma_gemm<64,64,2,false><<<dim3(1,16,48),256,S6464>>>(p);

    // proj + bias + residual(x) -> x2
    p=GP{}; p.Ah=pa; p.Bh=w2;
    p.K=768; p.lda=768; p.ldb=768; p.bias=b_proj; p.res=x; p.outf=px2; p.ldo=768;
    mma_gemm<64,128,3,true><<<dim3(6,64,1),256,S64128>>>(p);

    ln_kernel<<<ROWS,256>>>(px2,g2,be2,ph2,nullptr);
    dwln_kernel<<<ROWS,256>>>(ph2,dw_w,dw_b,gm,bm,pm);

    // fc1 + bias + gelu -> f
    p=GP{}; p.Ah=pm; p.Bh=w3;
    p.K=768; p.lda=768; p.ldb=768; p.bias=b_fc1; p.o1=pf; p.ldoh=3072;
    mma_gemm<128,128,4,true><<<dim3(24,32,1),256,S128128>>>(p);

    // fc2 + bias + residual(x2) -> out
    p=GP{}; p.Ah=pf; p.Bh=w4;
    p.K=3072; p.lda=3072; p.ldb=3072; p.bias=b_fc2; p.res=px2; p.outf=out; p.ldo=768;
    mma_gemm<64,128,3,true><<<dim3(6,64,1),256,S64128>>>(p);
}

// round 10
// speedup vs baseline: 5.5461x; 1.0930x over previous
#include <cuda_runtime.h>
#include <cuda_fp16.h>
#include <math.h>
#include <stdint.h>
typedef __half hf;

#define NHEAD 12
#define ROWS  4096
#define HSs   1048576LL

// ---------------- scratch ----------------
__device__ __align__(16) hf    g_S  [50331648];
__device__ __align__(16) hf    g_P  [50331648];
__device__ __align__(16) hf    g_q  [3145728];
__device__ __align__(16) hf    g_k  [3145728];
__device__ __align__(16) hf    g_v  [3145728];
__device__ __align__(16) hf    g_h1 [3145728];
__device__ __align__(16) hf    g_a  [3145728];
__device__ __align__(16) hf    g_m  [3145728];
__device__ __align__(16) hf    g_f  [12582912];
__device__ __align__(16) float g_x2 [3145728], g_h2[3145728];
__device__ __align__(16) hf    g_w1 [1769472];
__device__ __align__(16) hf    g_w2 [589824];
__device__ __align__(16) hf    g_w3 [2359296];
__device__ __align__(16) hf    g_w4 [2359296];

__device__ __forceinline__ uint32_t smem_u32(const void* p){
    uint32_t a; asm("{ .reg .u64 t; cvta.to.shared.u64 t, %1; cvt.u32.u64 %0, t; }":"=r"(a):"l"(p)); return a;
}
#define LDM4(r0,r1,r2,r3,ad) asm volatile("ldmatrix.sync.aligned.m8n8.x4.shared.b16 {%0,%1,%2,%3},[%4];" \
    : "=r"(r0),"=r"(r1),"=r"(r2),"=r"(r3):"r"(ad))
#define LDM4T(r0,r1,r2,r3,ad) asm volatile("ldmatrix.sync.aligned.m8n8.x4.trans.shared.b16 {%0,%1,%2,%3},[%4];" \
    : "=r"(r0),"=r"(r1),"=r"(r2),"=r"(r3):"r"(ad))
#define MMA(d,a,b) asm volatile( \
    "mma.sync.aligned.m16n8k16.row.col.f32.f16.f16.f32 {%0,%1,%2,%3},{%4,%5,%6,%7},{%8,%9},{%0,%1,%2,%3};" \
    : "+f"((d)[0]),"+f"((d)[1]),"+f"((d)[2]),"+f"((d)[3]) \
    : "r"((a)[0]),"r"((a)[1]),"r"((a)[2]),"r"((a)[3]),"r"((b)[0]),"r"((b)[1]))
#define CPA(dst,src) asm volatile("cp.async.cg.shared.global [%0],[%1],16;"::"r"(dst),"l"(src))
#define CPCOMMIT()   asm volatile("cp.async.commit_group;":::"memory")
#define CPWAIT0()    asm volatile("cp.async.wait_group 0;":::"memory")
#define CPWAIT1()    asm volatile("cp.async.wait_group 1;":::"memory")

__device__ __forceinline__ void st_h2(hf* p, float a, float b){
    __half2 t; t.x=__float2half_rn(a); t.y=__float2half_rn(b); *(__half2*)p = t;
}

struct GP {
    const hf *Ah,*Bh;
    int K, lda, ldb;
    long long sAz, sBz, sOz;
    float alpha;
    const float *bias, *res;
    float *outf; int ldo;
    hf *o1; int ldoh;
    hf *kd,*vd;
};

// C[M,N] = A[M,K] @ op(B), single fp16 product.
// BT=true: B is [N,K] k-contig. BT=false: B is [K,N] n-contig (trans ldmatrix).
// 3-stage cp.async pipeline (degenerates gracefully for T==1).
// EPI: 0=alpha->fp16 batched, 1=QKV scatter, 2=AV->[B,N,C] fp16, 3=bias+res f32, 4=bias+gelu fp16
template<int BM,int BN,int BK,int EPI,bool BT>
__global__ void __launch_bounds__(256) mma_gemm(GP p){
    constexpr int WARPS_N = BN/32;
    constexpr int WARPS_M = 8/WARPS_N;
    constexpr int WM = BM/WARPS_M;
    constexpr int MT = WM/16;
    constexpr int APAD = BK+8;
    constexpr int BPAD = BT ? (BK+8) : (BN+8);
    constexpr int ABYT = BM*APAD*2;
    constexpr int BBYT = BT ? (BN*BPAD*2) : (BK*BPAD*2);
    constexpr int STG  = ABYT + BBYT;

    extern __shared__ char dsm[];
    const uint32_t sb = smem_u32(dsm);
    const int tid=threadIdx.x, wid=tid>>5, lane=tid&31;
    const int z=blockIdx.z, m0=blockIdx.y*BM, n0=blockIdx.x*BN;
    const int wm_=wid/WARPS_N, wn_=wid%WARPS_N;

    const hf* Ah=p.Ah+(long long)z*p.sAz;
    const hf* Bh=p.Bh+(long long)z*p.sBz;

    float acc[MT][4][4];
    #pragma unroll
    for(int i=0;i<MT;i++)
        #pragma unroll
        for(int j=0;j<4;j++)
            #pragma unroll
            for(int e=0;e<4;e++) acc[i][j][e]=0.f;

    auto load_stage=[&](int t,int s){
        const long long k0=(long long)t*BK;
        const uint32_t b0 = sb + s*STG;
        #pragma unroll
        for(int i=tid;i<BM*(BK/8);i+=256){
            int row=i/(BK/8), seg=i%(BK/8);
            uint32_t d = b0 + (row*APAD+seg*8)*2;
            long long g=(long long)(m0+row)*p.lda + k0 + seg*8;
            CPA(d, Ah+g);
        }
        if(BT){
            #pragma unroll
            for(int i=tid;i<BN*(BK/8);i+=256){
                int row=i/(BK/8), seg=i%(BK/8);
                uint32_t d=b0+ABYT+(row*BPAD+seg*8)*2;
                long long g=(long long)(n0+row)*p.ldb + k0 + seg*8;
                CPA(d, Bh+g);
            }
        } else {
            #pragma unroll
            for(int i=tid;i<BK*(BN/8);i+=256){
                int row=i/(BN/8), seg=i%(BN/8);
                uint32_t d=b0+ABYT+(row*BPAD+seg*8)*2;
                long long g=(long long)(k0+row)*p.ldb + n0 + seg*8;
                CPA(d, Bh+g);
            }
        }
        CPCOMMIT();
    };

    auto compute=[&](int s){
        const uint32_t bA=sb+s*STG, bB=bA+ABYT;
        #pragma unroll
        for(int kk=0;kk<BK;kk+=16){
            uint32_t bh[4][2];
            #pragma unroll
            for(int nt=0;nt<2;nt++){
                if(BT){
                    int row = wn_*32 + nt*16 + (lane&7) + ((lane>>4)&1)*8;
                    int ko  = kk + ((lane>>3)&1)*8;
                    uint32_t off=(uint32_t)(row*BPAD+ko)*2;
                    LDM4(bh[2*nt][0],bh[2*nt][1],bh[2*nt+1][0],bh[2*nt+1][1], bB+off);
                } else {
                    int kb = kk + (lane&7) + ((lane>>3)&1)*8;
                    int nb = wn_*32 + nt*16 + ((lane>>4)&1)*8;
                    uint32_t off=(uint32_t)(kb*BPAD+nb)*2;
                    LDM4T(bh[2*nt][0],bh[2*nt][1],bh[2*nt+1][0],bh[2*nt+1][1], bB+off);
                }
            }
            #pragma unroll
            for(int mi=0;mi<MT;mi++){
                int row = wm_*WM + mi*16 + (lane&7) + ((lane>>3)&1)*8;
                int ko  = kk + ((lane>>4)&1)*8;
                uint32_t off=(uint32_t)(row*APAD+ko)*2;
                uint32_t ah[4];
                LDM4(ah[0],ah[1],ah[2],ah[3], bA+off);
                #pragma unroll
                for(int ni=0;ni<4;ni++) MMA(acc[mi][ni],ah,bh[ni]);
            }
        }
    };

    const int T = p.K/BK;
    load_stage(0,0);
    if(T>1) load_stage(1,1);
    for(int t=0;t<T;t++){
        if(t+1<T){ CPWAIT1(); } else { CPWAIT0(); }
        __syncthreads();
        if(t+2<T) load_stage(t+2,(t+2)%3);
        compute(t%3);
    }

    // -------- epilogue --------
    const int rb = m0 + wm_*WM, cbse = n0 + wn_*32;
    #pragma unroll
    for(int mi=0;mi<MT;mi++){
        #pragma unroll
        for(int ni=0;ni<4;ni++){
            #pragma unroll
            for(int half=0;half<2;half++){
                int r = rb + mi*16 + (lane>>2) + half*8;
                int c = cbse + ni*8 + (lane&3)*2;
                float v0=acc[mi][ni][half*2], v1=acc[mi][ni][half*2+1];
                if(EPI==0){
                    st_h2(p.o1 + (long long)z*p.sOz + (long long)r*p.ldo + c,
                          v0*p.alpha, v1*p.alpha);
                } else if(EPI==1){
                    v0+=p.bias[c]; v1+=p.bias[c+1];
                    int b=r>>10, n=r&1023;
                    hf* dst = (c<768)?p.o1 : ((c<1536)?p.kd:p.vd);
                    int cc  = (c<768)?c   : ((c<1536)?c-768:c-1536);
                    int hh=cc>>6, d=cc&63;
                    long long o=((long long)(b*12+hh)*1024+n)*64+d;
                    st_h2(dst+o, v0, v1);
                } else if(EPI==2){
                    int b=z/12, hh=z-b*12;
                    long long o=(long long)(b*1024+r)*768 + hh*64 + c;
                    st_h2(p.o1+o, v0, v1);
                } else if(EPI==3){
                    long long o=(long long)r*p.ldo + c;
                    float2 rr=*(const float2*)(p.res+o);
                    float2 ov; ov.x=v0+p.bias[c]+rr.x; ov.y=v1+p.bias[c+1]+rr.y;
                    *(float2*)(p.outf+o)=ov;
                } else if(EPI==4){
                    v0+=p.bias[c]; v1+=p.bias[c+1];
                    v0=0.5f*v0*(1.0f+erff(v0*0.70710678118654752f));
                    v1=0.5f*v1*(1.0f+erff(v1*0.70710678118654752f));
                    st_h2(p.o1+(long long)r*p.ldoh+c, v0, v1);
                }
            }
        }
    }
}

// ---------------- LayerNorm body (callable) ----------------
__device__ __forceinline__ void ln_body(const float* x, const float* g, const float* b,
                                        float* outf, hf* oh, long long row, int tid){
    float xv[3], s=0.f, ss=0.f;
    #pragma unroll
    for(int i=0;i<3;i++){ float v=x[tid+i*256]; xv[i]=v; s+=v; ss+=v*v; }
    __shared__ float red[64];
    #pragma unroll
    for(int o=16;o>0;o>>=1){ s+=__shfl_down_sync(~0u,s,o); ss+=__shfl_down_sync(~0u,ss,o); }
    int warp=tid>>5, lane=tid&31;
    if(lane==0){ red[warp]=s; red[32+warp]=ss; }
    __syncthreads();
    if(warp==0){
        s=(lane<8)?red[lane]:0.f; ss=(lane<8)?red[32+lane]:0.f;
        #pragma unroll
        for(int o=4;o>0;o>>=1){ s+=__shfl_down_sync(~0u,s,o); ss+=__shfl_down_sync(~0u,ss,o); }
        if(lane==0){ red[0]=s; red[1]=ss; }
    }
    __syncthreads();
    float mu=red[0]*(1.f/768), var=red[1]*(1.f/768)-mu*mu, rstd=rsqrtf(var+1e-5f);
    #pragma unroll
    for(int i=0;i<3;i++){
        int c=tid+i*256;
        float v=(xv[i]-mu)*rstd*g[c]+b[c];
        long long o=row*768+c;
        if(outf) outf[o]=v;
        if(oh) oh[o]=__float2half_rn(v);
    }
}

__global__ void ln_kernel(const float* __restrict__ in, const float* __restrict__ g,
                          const float* __restrict__ b, float* __restrict__ outf,
                          hf* __restrict__ oh){
    ln_body(in + (long long)blockIdx.x*768, g, b, outf, oh, blockIdx.x, threadIdx.x);
}

// ---------------- fused wconv + ln1 ----------------
__global__ void pre_kernel(const float* __restrict__ x, const float* __restrict__ g1,
                           const float* __restrict__ be1, hf* __restrict__ oh,
                           const float* __restrict__ w1,const float* __restrict__ w2,
                           const float* __restrict__ w3,const float* __restrict__ w4,
                           hf* o1,hf* o2,hf* o3,hf* o4){
    int bid=blockIdx.x;
    if(bid<4096){
        ln_body(x + (long long)bid*768, g1, be1, nullptr, oh, bid, threadIdx.x);
    } else {
        int i=(bid-4096)*256+threadIdx.x;
        const float* s; hf *ohw; int j=i;
        if(j<1769472){ s=w1; ohw=o1; }
        else if((j-=1769472)<589824){ s=w2; ohw=o2; }
        else if((j-=589824)<2359296){ s=w3; ohw=o3; }
        else { j-=2359296; s=w4; ohw=o4; }
        ohw[j]=__float2half_rn(s[j]);
    }
}

// ---------------- fused mix->softmax->mix ----------------
__global__ void __launch_bounds__(256) mixsoftmax(
    const hf* __restrict__ S, hf* __restrict__ P,
    const float* __restrict__ tb, const float* __restrict__ ta){
    extern __shared__ __half2 sh2[];
    __shared__ float tbs[144], tas[144], wsum[8][12], rin[12];
    int tid=threadIdx.x, warp=tid>>5, lane=tid&31;
    if(tid<144){ tbs[tid]=tb[tid]; tas[tid]=ta[tid]; }
    __syncthreads();
    int bn=blockIdx.x, b=bn>>10, n=bn&1023;
    long long base=((long long)b*NHEAD*1024+n)*1024;
    float sm[12];
    #pragma unroll
    for(int g=0;g<12;g++) sm[g]=0.f;
    #pragma unroll 1
    for(int jj=0;jj<2;jj++){
        int mp=tid+jj*256;
        float2 s[12];
        #pragma unroll
        for(int h=0;h<12;h++) s[h]=__half22float2(*(const __half2*)(S+base+h*HSs+2*mp));
        #pragma unroll
        for(int g=0;g<12;g++){
            float v0=0.f, v1=0.f;
            #pragma unroll
            for(int h=0;h<12;h++){ v0=fmaf(tbs[g*12+h],s[h].x,v0); v1=fmaf(tbs[g*12+h],s[h].y,v1); }
            float e0=__expf(v0), e1=__expf(v1);
            sh2[g*512+mp]=__floats2half2_rn(e0,e1);
            sm[g]+=e0+e1;
        }
    }
    #pragma unroll
    for(int o=16;o>0;o>>=1){
        #pragma unroll
        for(int g=0;g<12;g++) sm[g]+=__shfl_xor_sync(~0u,sm[g],o);
    }
    if(lane==0){
        #pragma unroll
        for(int g=0;g<12;g++) wsum[warp][g]=sm[g];
    }
    __syncthreads();
    if(tid<12){
        float t=0.f;
        #pragma unroll
        for(int w=0;w<8;w++) t+=wsum[w][tid];
        rin[tid]=1.f/t;
    }
    __syncthreads();
    float RS[12];
    #pragma unroll
    for(int g=0;g<12;g++) RS[g]=rin[g];
    #pragma unroll 1
    for(int jj=0;jj<2;jj++){
        int mp=tid+jj*256;
        float2 e[12];
        #pragma unroll
        for(int h=0;h<12;h++){
            e[h]=__half22float2(sh2[h*512+mp]);
            e[h].x*=RS[h]; e[h].y*=RS[h];
        }
        #pragma unroll
        for(int g=0;g<12;g++){
            float v0=0.f, v1=0.f;
            #pragma unroll
            for(int h=0;h<12;h++){ v0=fmaf(tas[g*12+h],e[h].x,v0); v1=fmaf(tas[g*12+h],e[h].y,v1); }
            *(__half2*)(P+base+g*HSs+2*mp)=__floats2half2_rn(v0,v1);
        }
    }
}

// ---------------- fused depthwise conv + LN(gm,bm) ----------------
__global__ void dwln_kernel(const float* __restrict__ in, const float* __restrict__ w,
                            const float* __restrict__ bias, const float* __restrict__ gm,
                            const float* __restrict__ bm, hf* __restrict__ om){
    int row=blockIdx.x, tid=threadIdx.x;
    int b=row>>10, n=row&1023;
    const float* xp = in + (long long)b*1024*768;
    float acc[3], s=0.f, ss=0.f;
    #pragma unroll
    for(int i=0;i<3;i++){
        int c=tid+i*256;
        float a=bias[c];
        #pragma unroll
        for(int k=0;k<7;k++){
            int m=n+k-3;
            if(m>=0 && m<1024) a+=w[c*7+k]*xp[(long long)m*768+c];
        }
        acc[i]=a; s+=a; ss+=a*a;
    }
    __shared__ float red[64];
    #pragma unroll
    for(int o=16;o>0;o>>=1){ s+=__shfl_down_sync(~0u,s,o); ss+=__shfl_down_sync(~0u,ss,o); }
    int warp=tid>>5, lane=tid&31;
    if(lane==0){ red[warp]=s; red[32+warp]=ss; }
    __syncthreads();
    if(warp==0){
        s=(lane<8)?red[lane]:0.f; ss=(lane<8)?red[32+lane]:0.f;
        #pragma unroll
        for(int o=4;o>0;o>>=1){ s+=__shfl_down_sync(~0u,s,o); ss+=__shfl_down_sync(~0u,ss,o); }
        if(lane==0){ red[0]=s; red[1]=ss; }
    }
    __syncthreads();
    float mu=red[0]*(1.f/768), var=red[1]*(1.f/768)-mu*mu, rstd=rsqrtf(var+1e-5f);
    #pragma unroll
    for(int i=0;i<3;i++){
        int c=tid+i*256;
        om[(long long)row*768+c]=__float2half_rn((acc[i]-mu)*rstd*gm[c]+bm[c]);
    }
}

// ---------------- launch ----------------
extern "C" void kernel_launch(void* const* d_in, const int* in_sizes, int n_in,
                              void* d_out, int out_size){
    const float *x=(const float*)d_in[0], *w_qkv=(const float*)d_in[1], *b_qkv=(const float*)d_in[2];
    const float *w_proj=(const float*)d_in[3], *b_proj=(const float*)d_in[4];
    const float *w_fc1=(const float*)d_in[5], *b_fc1=(const float*)d_in[6];
    const float *w_fc2=(const float*)d_in[7], *b_fc2=(const float*)d_in[8];
    const float *t_before=(const float*)d_in[9], *t_after=(const float*)d_in[10];
    const float *g1=(const float*)d_in[11], *be1=(const float*)d_in[12];
    const float *g2=(const float*)d_in[13], *be2=(const float*)d_in[14];
    const float *dw_w=(const float*)d_in[15], *dw_b=(const float*)d_in[16];
    const float *gm=(const float*)d_in[17], *bm=(const float*)d_in[18];
    float* out=(float*)d_out;

    float *px2,*ph2;
    hf *pS,*pP,*pq,*pk,*pv,*ph1,*pa,*pm,*pf,*w1,*w2,*w3,*w4;
    cudaGetSymbolAddress((void**)&pS,g_S);   cudaGetSymbolAddress((void**)&px2,g_x2);
    cudaGetSymbolAddress((void**)&ph2,g_h2);
    cudaGetSymbolAddress((void**)&pP,g_P);   cudaGetSymbolAddress((void**)&pq,g_q);
    cudaGetSymbolAddress((void**)&pk,g_k);   cudaGetSymbolAddress((void**)&pv,g_v);
    cudaGetSymbolAddress((void**)&ph1,g_h1); cudaGetSymbolAddress((void**)&pa,g_a);
    cudaGetSymbolAddress((void**)&pm,g_m);   cudaGetSymbolAddress((void**)&pf,g_f);
    cudaGetSymbolAddress((void**)&w1,g_w1);  cudaGetSymbolAddress((void**)&w2,g_w2);
    cudaGetSymbolAddress((void**)&w3,g_w3);  cudaGetSymbolAddress((void**)&w4,g_w4);

    // smem sizes
    const int S_QKV = 3*((128*40 + 128*40)*2);          // 61440  (BK=32, BT)
    const int S_QK  = 1*((128*72 + 64*72)*2);           // 27648  (BK=64 single stage)
    const int S_AV  = 3*((64*40)*2 + (32*72)*2);        // 29184  (BK=32, trans)
    const int S_PRJ = 3*((64*40 + 128*40)*2);           // 46080
    const int S_FC1 = 3*((128*40 + 128*40)*2);          // 61440
    const int SMIX  = 12*512*4;                          // 24576
    cudaFuncSetAttribute(mma_gemm<128,128,32,1,true>, cudaFuncAttributeMaxDynamicSharedMemorySize, S_QKV);
    cudaFuncSetAttribute(mma_gemm<128,64,64,0,true>,  cudaFuncAttributeMaxDynamicSharedMemorySize, S_QK);
    cudaFuncSetAttribute(mma_gemm<64,64,32,2,false>,  cudaFuncAttributeMaxDynamicSharedMemorySize, S_AV);
    cudaFuncSetAttribute(mma_gemm<64,128,32,3,true>,  cudaFuncAttributeMaxDynamicSharedMemorySize, S_PRJ);
    cudaFuncSetAttribute(mma_gemm<128,128,32,4,true>, cudaFuncAttributeMaxDynamicSharedMemorySize, S_FC1);
    cudaFuncSetAttribute(mixsoftmax, cudaFuncAttributeMaxDynamicSharedMemorySize, SMIX);

    // fused ln1 + weight convert: 4096 LN blocks + 27648 wconv blocks
    pre_kernel<<<4096+27648,256>>>(x,g1,be1,ph1, w_qkv,w_proj,w_fc1,w_fc2, w1,w2,w3,w4);

    GP p{};
    // QKV: h1 @ w_qkv^T + b -> q, k, v
    p.Ah=ph1; p.Bh=w1; p.K=768; p.lda=768; p.ldb=768;
    p.bias=b_qkv; p.o1=pq; p.kd=pk; p.vd=pv;
    mma_gemm<128,128,32,1,true><<<dim3(18,32,1),256,S_QKV>>>(p);

    // QK^T per (b,h): S = Q K^T * 0.125 — single-stage BK=64
    p=GP{}; p.Ah=pq; p.Bh=pk;
    p.K=64; p.lda=64; p.ldb=64; p.sAz=65536; p.sBz=65536; p.sOz=HSs;
    p.o1=pS; p.ldo=1024; p.alpha=0.125f;
    mma_gemm<128,64,64,0,true><<<dim3(16,8,48),256,S_QK>>>(p);

    mixsoftmax<<<ROWS,256,SMIX>>>(pS,pP,t_before,t_after);

    // AV per (b,h): P[1024,1024] @ V[1024,64] (B row-major via trans-ldmatrix)
    p=GP{}; p.Ah=pP; p.Bh=pv;
    p.K=1024; p.lda=1024; p.ldb=64; p.sAz=HSs; p.sBz=65536;
    p.o1=pa;
    mma_gemm<64,64,32,2,false><<<dim3(1,16,48),256,S_AV>>>(p);

    // proj + bias + residual(x) -> x2
    p=GP{}; p.Ah=pa; p.Bh=w2;
    p.K=768; p.lda=768; p.ldb=768; p.bias=b_proj; p.res=x; p.outf=px2; p.ldo=768;
    mma_gemm<64,128,32,3,true><<<dim3(6,64,1),256,S_PRJ>>>(p);

    ln_kernel<<<ROWS,256>>>(px2,g2,be2,ph2,nullptr);
    dwln_kernel<<<ROWS,256>>>(ph2,dw_w,dw_b,gm,bm,pm);

    // fc1 + bias + gelu -> f
    p=GP{}; p.Ah=pm; p.Bh=w3;
    p.K=768; p.lda=768; p.ldb=768; p.bias=b_fc1; p.o1=pf; p.ldoh=3072;
    mma_gemm<128,128,32,4,true><<<dim3(24,32,1),256,S_FC1>>>(p);

    // fc2 + bias + residual(x2) -> out
    p=GP{}; p.Ah=pf; p.Bh=w4;
    p.K=3072; p.lda=3072; p.ldb=3072; p.bias=b_fc2; p.res=px2; p.outf=out; p.ldo=768;
    mma_gemm<64,128,32,3,true><<<dim3(6,64,1),256,S_PRJ>>>(p);
}